// round 2
// baseline (speedup 1.0000x reference)
#include <cuda_runtime.h>
#include <cuda_bf16.h>
#include <cstdio>

#define N_B    4
#define S_LEN  2048
#define EMB    1024
#define HEADS  16
#define HD     64

// ---------------- scratch (device globals; no allocation allowed) ----------
__device__ float g_q[N_B * HEADS * S_LEN * HD];   // [n][h][s][d]
__device__ float g_k[N_B * HEADS * S_LEN * HD];
__device__ float g_v[N_B * HEADS * S_LEN * HD];
__device__ float g_ao[N_B * S_LEN * EMB];         // attention output, [n][s][h*64+d]

// ---------------------------------------------------------------------------
// Kernel 1: per-head linear projections  y = x @ W^T   (W: 64x64, shared by all heads)
// grid: (S_LEN/32, N_B*HEADS, 3)   block: 256
// z=0: queries->g_q (Wq), z=1: keys->g_k (Wk), z=2: values->g_v (Wv)
// ---------------------------------------------------------------------------
__global__ __launch_bounds__(256)
void proj_kernel(const float* __restrict__ xq, const float* __restrict__ xk,
                 const float* __restrict__ xv,
                 const float* __restrict__ Wq, const float* __restrict__ Wk,
                 const float* __restrict__ Wv)
{
    __shared__ float Ws[64 * 68];   // Ws[e*68+d] = W[e][d], padded: conflict-free f4 reads
    __shared__ float Xs[32 * 64];   // Xs[r*64+d]

    const int which = blockIdx.z;
    const float* X; const float* W; float* Y;
    if (which == 0)      { X = xq; W = Wq; Y = g_q; }
    else if (which == 1) { X = xk; W = Wk; Y = g_k; }
    else                 { X = xv; W = Wv; Y = g_v; }

    const int nh = blockIdx.y;
    const int n  = nh / HEADS;
    const int h  = nh % HEADS;
    const int s0 = blockIdx.x * 32;
    const int tid = threadIdx.x;

    for (int i = tid; i < 64 * 64; i += 256) {
        int e = i >> 6, d = i & 63;
        Ws[e * 68 + d] = W[i];
    }
    for (int i = tid; i < 32 * 64; i += 256) {
        int r = i >> 6, d = i & 63;
        Xs[i] = X[(n * S_LEN + s0 + r) * EMB + h * HD + d];
    }
    __syncthreads();

    const int e     = tid & 63;
    const int rbase = (tid >> 6) * 8;   // 8 rows per thread

    float acc[8];
#pragma unroll
    for (int r = 0; r < 8; r++) acc[r] = 0.f;

#pragma unroll 4
    for (int d4 = 0; d4 < 64; d4 += 4) {
        const float4 w = *(const float4*)&Ws[e * 68 + d4];
#pragma unroll
        for (int r = 0; r < 8; r++) {
            const float4 x = *(const float4*)&Xs[(rbase + r) * 64 + d4];
            acc[r] += x.x * w.x + x.y * w.y + x.z * w.z + x.w * w.w;
        }
    }

#pragma unroll
    for (int r = 0; r < 8; r++) {
        Y[((n * HEADS + h) * S_LEN + s0 + rbase + r) * HD + e] = acc[r];
    }
}

// ---------------------------------------------------------------------------
// Kernel 2: flash attention per (n, h, q-tile of 64)
// grid: (HEADS, S_LEN/64, N_B)   block: 256 (16x16 thread grid, 4x4 micro-tiles)
// dynamic smem: Qt[64*68] + Kt[64*68] + Vs[64*64] + Ps[64*65] floats = 67840 B
// ---------------------------------------------------------------------------
#define ATTN_SMEM_FLOATS (64*68 + 64*68 + 64*64 + 64*65)
#define ATTN_SMEM_BYTES  (ATTN_SMEM_FLOATS * 4)

__global__ __launch_bounds__(256, 2)
void attn_kernel(const int* __restrict__ mask)
{
    extern __shared__ float sm[];
    float* Qs = sm;                    // [d*68 + q]  (transposed)
    float* Ks = Qs + 64 * 68;          // [d*68 + k]  (transposed)
    float* Vs = Ks + 64 * 68;          // [k*64 + d]  (natural)
    float* Ps = Vs + 64 * 64;          // [q*65 + k]

    const int h  = blockIdx.x;
    const int qt = blockIdx.y;
    const int n  = blockIdx.z;
    const int q0 = qt * 64;

    const float* Q = g_q + (size_t)(n * HEADS + h) * S_LEN * HD;
    const float* K = g_k + (size_t)(n * HEADS + h) * S_LEN * HD;
    const float* V = g_v + (size_t)(n * HEADS + h) * S_LEN * HD;
    const int*   M = mask + n * S_LEN * S_LEN;

    const int tid = threadIdx.x;
    const int tx  = tid & 15;          // k / d quadrant (4 cols each)
    const int ty  = tid >> 4;          // q quadrant (4 rows each)

    // stage Q transposed (one-time)
    for (int i = tid; i < 64 * 64; i += 256) {
        int q = i >> 6, d = i & 63;
        Qs[d * 68 + q] = Q[(q0 + q) * HD + d];
    }

    float o[4][4];
    float m_r[4], l_r[4];
#pragma unroll
    for (int i = 0; i < 4; i++) {
        m_r[i] = -1e30f; l_r[i] = 0.f;
#pragma unroll
        for (int j = 0; j < 4; j++) o[i][j] = 0.f;
    }

    const float INV_SQRT_E = 0.03125f;   // 1/sqrt(1024)

    for (int k0 = 0; k0 < S_LEN; k0 += 64) {
        __syncthreads();   // protect smem reuse (also orders Q staging on iter 0)

        // stage K (transposed) and V
        for (int i = tid; i < 64 * 64; i += 256) {
            int k = i >> 6, d = i & 63;
            float kv = K[(k0 + k) * HD + d];
            Ks[d * 68 + k] = kv;
            Vs[i]          = V[(k0 + k) * HD + d];
        }

        // prefetch this thread's mask block (overlaps with staging/sync)
        int mreg[4][4];
#pragma unroll
        for (int i = 0; i < 4; i++)
#pragma unroll
            for (int j = 0; j < 4; j++)
                mreg[i][j] = M[(q0 + ty * 4 + i) * S_LEN + k0 + tx * 4 + j];

        __syncthreads();

        // ---- scores: s[i][j] = Q[q] . K[k] ----
        float s[4][4];
#pragma unroll
        for (int i = 0; i < 4; i++)
#pragma unroll
            for (int j = 0; j < 4; j++) s[i][j] = 0.f;

#pragma unroll 2
        for (int d = 0; d < 64; d++) {
            const float4 qv = *(const float4*)&Qs[d * 68 + (ty << 2)];
            const float4 kv = *(const float4*)&Ks[d * 68 + (tx << 2)];
            const float qa[4] = {qv.x, qv.y, qv.z, qv.w};
            const float ka[4] = {kv.x, kv.y, kv.z, kv.w};
#pragma unroll
            for (int i = 0; i < 4; i++)
#pragma unroll
                for (int j = 0; j < 4; j++)
                    s[i][j] = fmaf(qa[i], ka[j], s[i][j]);
        }

        // mask, then scale (matches reference: mask applied before /sqrt(E))
#pragma unroll
        for (int i = 0; i < 4; i++)
#pragma unroll
            for (int j = 0; j < 4; j++)
                s[i][j] = mreg[i][j] ? s[i][j] * INV_SQRT_E : -1e30f;

        // ---- online softmax (row groups = 16 threads sharing ty) ----
#pragma unroll
        for (int i = 0; i < 4; i++) {
            float mt = fmaxf(fmaxf(s[i][0], s[i][1]), fmaxf(s[i][2], s[i][3]));
            mt = fmaxf(mt, __shfl_xor_sync(0xffffffffu, mt, 1));
            mt = fmaxf(mt, __shfl_xor_sync(0xffffffffu, mt, 2));
            mt = fmaxf(mt, __shfl_xor_sync(0xffffffffu, mt, 4));
            mt = fmaxf(mt, __shfl_xor_sync(0xffffffffu, mt, 8));

            const float mn   = fmaxf(m_r[i], mt);
            const float corr = __expf(m_r[i] - mn);
            m_r[i] = mn;

            float ps = 0.f;
#pragma unroll
            for (int j = 0; j < 4; j++) {
                float p = __expf(s[i][j] - mn);
                Ps[(ty * 4 + i) * 65 + (tx << 2) + j] = p;
                ps += p;
            }
            ps += __shfl_xor_sync(0xffffffffu, ps, 1);
            ps += __shfl_xor_sync(0xffffffffu, ps, 2);
            ps += __shfl_xor_sync(0xffffffffu, ps, 4);
            ps += __shfl_xor_sync(0xffffffffu, ps, 8);

            l_r[i] = l_r[i] * corr + ps;
#pragma unroll
            for (int j = 0; j < 4; j++) o[i][j] *= corr;
        }
        __syncthreads();

        // ---- o += P @ V ----
#pragma unroll 2
        for (int k = 0; k < 64; k++) {
            const float4 vv = *(const float4*)&Vs[(k << 6) + (tx << 2)];
            const float va[4] = {vv.x, vv.y, vv.z, vv.w};
#pragma unroll
            for (int i = 0; i < 4; i++) {
                const float p = Ps[(ty * 4 + i) * 65 + k];
#pragma unroll
                for (int j = 0; j < 4; j++)
                    o[i][j] = fmaf(p, va[j], o[i][j]);
            }
        }
    }

    // epilogue: normalize, write [n][s][h*64+d]
#pragma unroll
    for (int i = 0; i < 4; i++) {
        const float inv = 1.0f / l_r[i];
        float4 r;
        r.x = o[i][0] * inv; r.y = o[i][1] * inv;
        r.z = o[i][2] * inv; r.w = o[i][3] * inv;
        *(float4*)&g_ao[(size_t)(n * S_LEN + q0 + ty * 4 + i) * EMB + h * HD + (tx << 2)] = r;
    }
}

// ---------------------------------------------------------------------------
// Kernel 3: output projection  out = g_ao @ Wo^T + bo
// C[r][e] = sum_c A[r][c] * Wo[e][c] + bo[e]
// grid: (EMB/64, N_B*S_LEN/64)  block: 256, 64x64 tile, BK=32, 4x4 micro-tiles
// ---------------------------------------------------------------------------
__global__ __launch_bounds__(256)
void out_gemm_kernel(const float* __restrict__ Wo, const float* __restrict__ bo,
                     float* __restrict__ out)
{
    __shared__ float Ast[32 * 68];   // [c*68 + r]
    __shared__ float Bst[32 * 68];   // [c*68 + e]

    const int r0 = blockIdx.y * 64;
    const int e0 = blockIdx.x * 64;
    const int tid = threadIdx.x;
    const int tx  = tid & 15;
    const int ty  = tid >> 4;

    float acc[4][4];
#pragma unroll
    for (int i = 0; i < 4; i++)
#pragma unroll
        for (int j = 0; j < 4; j++) acc[i][j] = 0.f;

    for (int c0 = 0; c0 < EMB; c0 += 32) {
        __syncthreads();
        for (int i = tid; i < 64 * 32; i += 256) {
            int r = i >> 5, c = i & 31;
            Ast[c * 68 + r] = g_ao[(size_t)(r0 + r) * EMB + c0 + c];
            Bst[c * 68 + r] = Wo[(size_t)(e0 + r) * EMB + c0 + c];
        }
        __syncthreads();

#pragma unroll 8
        for (int c = 0; c < 32; c++) {
            const float4 a = *(const float4*)&Ast[c * 68 + (ty << 2)];
            const float4 b = *(const float4*)&Bst[c * 68 + (tx << 2)];
            const float aa[4] = {a.x, a.y, a.z, a.w};
            const float bb[4] = {b.x, b.y, b.z, b.w};
#pragma unroll
            for (int i = 0; i < 4; i++)
#pragma unroll
                for (int j = 0; j < 4; j++)
                    acc[i][j] = fmaf(aa[i], bb[j], acc[i][j]);
        }
    }

    const float4 bv = *(const float4*)&bo[e0 + (tx << 2)];
    const float bb[4] = {bv.x, bv.y, bv.z, bv.w};
#pragma unroll
    for (int i = 0; i < 4; i++) {
        float4 r;
        r.x = acc[i][0] + bb[0]; r.y = acc[i][1] + bb[1];
        r.z = acc[i][2] + bb[2]; r.w = acc[i][3] + bb[3];
        *(float4*)&out[(size_t)(r0 + ty * 4 + i) * EMB + e0 + (tx << 2)] = r;
    }
}

// ---------------------------------------------------------------------------
extern "C" void kernel_launch(void* const* d_in, const int* in_sizes, int n_in,
                              void* d_out, int out_size)
{
    const float* values  = (const float*)d_in[0];
    const float* queries = (const float*)d_in[1];
    const float* keys    = (const float*)d_in[2];
    const int*   mask    = (const int*)  d_in[3];
    const float* Wv      = (const float*)d_in[4];
    const float* Wk      = (const float*)d_in[5];
    const float* Wq      = (const float*)d_in[6];
    const float* Wo      = (const float*)d_in[7];
    const float* bo      = (const float*)d_in[8];
    float* out = (float*)d_out;

    static bool attr_set = false;  // attribute setting is idempotent & not a stream op
    if (!attr_set) {
        cudaFuncSetAttribute(attn_kernel,
                             cudaFuncAttributeMaxDynamicSharedMemorySize,
                             ATTN_SMEM_BYTES);
        attr_set = true;
    }

    // 1) projections (q, k, v)
    dim3 pgrid(S_LEN / 32, N_B * HEADS, 3);
    proj_kernel<<<pgrid, 256>>>(queries, keys, values, Wq, Wk, Wv);

    // 2) flash attention
    dim3 agrid(HEADS, S_LEN / 64, N_B);
    attn_kernel<<<agrid, 256, ATTN_SMEM_BYTES>>>(mask);

    // 3) output projection + bias
    dim3 ggrid(EMB / 64, (N_B * S_LEN) / 64);
    out_gemm_kernel<<<ggrid, 256>>>(Wo, bo, out);
}

// round 4
// speedup vs baseline: 1.7250x; 1.7250x over previous
#include <cuda_runtime.h>
#include <cuda_bf16.h>
#include <mma.h>
#include <cstdint>

using namespace nvcuda;

#define N_B    4
#define S_LEN  2048
#define EMB    1024
#define HEADS  16
#define HD     64
#define MWORDS (S_LEN / 32)

// ---------------- scratch (device globals; no allocation allowed) ----------
__device__ float g_q[N_B * HEADS * S_LEN * HD];   // [n][h][s][d]
__device__ float g_k[N_B * HEADS * S_LEN * HD];
__device__ float g_v[N_B * HEADS * S_LEN * HD];
__device__ float g_ao[N_B * S_LEN * EMB];         // attention out [n][s][h*64+d]
__device__ unsigned g_mbits[N_B * S_LEN * MWORDS];

// split two floats into packed bf16x2 hi + lo (residual)
__device__ __forceinline__ void split2(float x0, float x1, uint32_t& hi, uint32_t& lo) {
    __nv_bfloat16 h0 = __float2bfloat16_rn(x0), h1 = __float2bfloat16_rn(x1);
    float r0 = x0 - __bfloat162float(h0), r1 = x1 - __bfloat162float(h1);
    __nv_bfloat16 l0 = __float2bfloat16_rn(r0), l1 = __float2bfloat16_rn(r1);
    __nv_bfloat162 hp; hp.x = h0; hp.y = h1;
    __nv_bfloat162 lp; lp.x = l0; lp.y = l1;
    hi = *reinterpret_cast<uint32_t*>(&hp);
    lo = *reinterpret_cast<uint32_t*>(&lp);
}

// ---------------------------------------------------------------------------
// Kernel 0: pack mask into bitfields
// ---------------------------------------------------------------------------
__global__ __launch_bounds__(256)
void mask_pack_kernel(const int* __restrict__ mask)
{
    int gid  = blockIdx.x * 256 + threadIdx.x;
    int w    = gid >> 5;
    int lane = gid & 31;
    int v = mask[(size_t)w * 32 + lane];
    unsigned bits = __ballot_sync(0xffffffffu, v != 0);
    if (lane == 0) g_mbits[w] = bits;
}

// ---------------------------------------------------------------------------
// Kernel 1: per-head projections (unchanged from R2 — 190us, issue-bound)
// ---------------------------------------------------------------------------
__global__ __launch_bounds__(256)
void proj_kernel(const float* __restrict__ xq, const float* __restrict__ xk,
                 const float* __restrict__ xv,
                 const float* __restrict__ Wq, const float* __restrict__ Wk,
                 const float* __restrict__ Wv)
{
    __shared__ float Ws[64 * 68];
    __shared__ float Xs[32 * 64];

    const int which = blockIdx.z;
    const float* X; const float* W; float* Y;
    if (which == 0)      { X = xq; W = Wq; Y = g_q; }
    else if (which == 1) { X = xk; W = Wk; Y = g_k; }
    else                 { X = xv; W = Wv; Y = g_v; }

    const int nh = blockIdx.y;
    const int n  = nh / HEADS;
    const int h  = nh % HEADS;
    const int s0 = blockIdx.x * 32;
    const int tid = threadIdx.x;

    for (int i = tid; i < 64 * 64; i += 256) {
        int e = i >> 6, d = i & 63;
        Ws[e * 68 + d] = W[i];
    }
    for (int i = tid; i < 32 * 64; i += 256) {
        int r = i >> 6, d = i & 63;
        Xs[i] = X[(n * S_LEN + s0 + r) * EMB + h * HD + d];
    }
    __syncthreads();

    const int e     = tid & 63;
    const int rbase = (tid >> 6) * 8;

    float acc[8];
#pragma unroll
    for (int r = 0; r < 8; r++) acc[r] = 0.f;

#pragma unroll 4
    for (int d4 = 0; d4 < 64; d4 += 4) {
        const float4 w = *(const float4*)&Ws[e * 68 + d4];
#pragma unroll
        for (int r = 0; r < 8; r++) {
            const float4 x = *(const float4*)&Xs[(rbase + r) * 64 + d4];
            acc[r] += x.x * w.x + x.y * w.y + x.z * w.z + x.w * w.w;
        }
    }
#pragma unroll
    for (int r = 0; r < 8; r++)
        Y[((n * HEADS + h) * S_LEN + s0 + rbase + r) * HD + e] = acc[r];
}

// ---------------------------------------------------------------------------
// Kernel 2: wmma bf16 hi/lo flash attention
// grid (HEADS, S_LEN/128, N_B), 256 threads (8 warps x 16 q-rows)
// ---------------------------------------------------------------------------
#define PQK  72            // bf16 pitch for Q/K/V (mult of 8, odd 16B units)
#define PP   136           // bf16 pitch for P
#define PSCR 20            // float pitch for scratch (mult of 4)

#define A_QHI  0
#define A_QLO  18432
#define A_KHI  36864
#define A_KLO  55296
#define A_VHI  73728
#define A_VLO  92160
#define A_PHI  110592
#define A_PLO  145408
#define A_SCR  180224      // 8 warps * 16*20 floats = 10240
#define A_LRED 190464      // 128 floats
#define ATTN_SMEM_BYTES (190464 + 512)

// stage 128x64 f32 (row-major pitch 64) -> bf16 hi/lo smem pitch PQK
__device__ __forceinline__ void stage_hilo(const float* __restrict__ src,
                                           char* s_hi, char* s_lo, int tid)
{
    const int r    = tid >> 1;
    const int half = tid & 1;
    const float4* s4 = (const float4*)(src + (size_t)r * HD) + half * 8;
#pragma unroll
    for (int t = 0; t < 4; t++) {
        float4 a = s4[2 * t], b = s4[2 * t + 1];
        float f[8] = {a.x, a.y, a.z, a.w, b.x, b.y, b.z, b.w};
        uint32_t H[4], L[4];
#pragma unroll
        for (int u = 0; u < 4; u++) split2(f[2 * u], f[2 * u + 1], H[u], L[u]);
        uint32_t off = (uint32_t)(r * (PQK * 2) + half * 64 + t * 16);
        *(uint4*)(s_hi + off) = make_uint4(H[0], H[1], H[2], H[3]);
        *(uint4*)(s_lo + off) = make_uint4(L[0], L[1], L[2], L[3]);
    }
}

__global__ __launch_bounds__(256, 1)
void attn_wmma_kernel()
{
    extern __shared__ char sm[];
    __nv_bfloat16* Qhi = (__nv_bfloat16*)(sm + A_QHI);
    __nv_bfloat16* Qlo = (__nv_bfloat16*)(sm + A_QLO);
    __nv_bfloat16* Khi = (__nv_bfloat16*)(sm + A_KHI);
    __nv_bfloat16* Klo = (__nv_bfloat16*)(sm + A_KLO);
    __nv_bfloat16* Vhi = (__nv_bfloat16*)(sm + A_VHI);
    __nv_bfloat16* Vlo = (__nv_bfloat16*)(sm + A_VLO);
    __nv_bfloat16* Phi = (__nv_bfloat16*)(sm + A_PHI);
    __nv_bfloat16* Plo = (__nv_bfloat16*)(sm + A_PLO);
    float*         lred = (float*)(sm + A_LRED);

    const int tid = threadIdx.x, wid = tid >> 5, lane = tid & 31;
    const int h = blockIdx.x, qt = blockIdx.y, n = blockIdx.z;
    const int q0 = qt * 128;

    float* scr = (float*)(sm + A_SCR) + wid * (16 * PSCR);

    const float* Qg = g_q + (size_t)(n * HEADS + h) * S_LEN * HD + (size_t)q0 * HD;
    const float* Kg = g_k + (size_t)(n * HEADS + h) * S_LEN * HD;
    const float* Vg = g_v + (size_t)(n * HEADS + h) * S_LEN * HD;

    // stage Q once (visibility covered by first in-loop __syncthreads)
    stage_hilo(Qg, (char*)Qhi, (char*)Qlo, tid);

    const int r  = lane >> 1;         // row within warp's 16-row band
    const int cw = lane & 1;          // 8-col half within 16-col block
    const int qrow = wid * 16 + r;    // 0..127
    const unsigned* mrow = g_mbits + (size_t)(n * S_LEN + q0 + qrow) * MWORDS;

    wmma::fragment<wmma::accumulator, 16, 16, 16, float> oacc[4];
#pragma unroll
    for (int db = 0; db < 4; db++) wmma::fill_fragment(oacc[db], 0.0f);
    float lsum = 0.f;

    for (int it = 0; it < S_LEN / 128; it++) {
        const int k0 = it * 128;
        __syncthreads();   // previous iter's K/V reads done
        stage_hilo(Kg + (size_t)k0 * HD, (char*)Khi, (char*)Klo, tid);
        stage_hilo(Vg + (size_t)k0 * HD, (char*)Vhi, (char*)Vlo, tid);
        __syncthreads();   // staging visible

        // ---- S = QK^T for this warp's 16 rows, 8 col-blocks of 16 ----
#pragma unroll
        for (int nb = 0; nb < 8; nb++) {
            wmma::fragment<wmma::accumulator, 16, 16, 16, float> sacc;
            wmma::fill_fragment(sacc, 0.0f);
#pragma unroll
            for (int kk = 0; kk < 4; kk++) {
                wmma::fragment<wmma::matrix_a, 16, 16, 16, __nv_bfloat16, wmma::row_major> ah, al;
                wmma::fragment<wmma::matrix_b, 16, 16, 16, __nv_bfloat16, wmma::col_major> bh, bl;
                wmma::load_matrix_sync(ah, Qhi + wid * 16 * PQK + kk * 16, PQK);
                wmma::load_matrix_sync(al, Qlo + wid * 16 * PQK + kk * 16, PQK);
                wmma::load_matrix_sync(bh, Khi + nb * 16 * PQK + kk * 16, PQK);
                wmma::load_matrix_sync(bl, Klo + nb * 16 * PQK + kk * 16, PQK);
                wmma::mma_sync(sacc, ah, bh, sacc);
                wmma::mma_sync(sacc, ah, bl, sacc);
                wmma::mma_sync(sacc, al, bh, sacc);
            }
            wmma::store_matrix_sync(scr, sacc, PSCR, wmma::mem_row_major);
            __syncwarp();

            // mask + exp + pack to P hi/lo  (lane -> row r, cols cw*8..+7)
            unsigned word = mrow[it * 4 + (nb >> 1)];
            int shift = ((nb & 1) << 4) + (cw << 3);
            float p[8];
#pragma unroll
            for (int j = 0; j < 8; j++) {
                float e = __expf(scr[r * PSCR + cw * 8 + j] * 0.03125f);
                p[j] = ((word >> (shift + j)) & 1u) ? e : 0.f;
                lsum += p[j];
            }
            uint32_t H[4], L[4];
#pragma unroll
            for (int u = 0; u < 4; u++) split2(p[2 * u], p[2 * u + 1], H[u], L[u]);
            uint32_t off = (uint32_t)(qrow * (PP * 2) + nb * 32 + cw * 16);
            *(uint4*)((char*)Phi + off) = make_uint4(H[0], H[1], H[2], H[3]);
            *(uint4*)((char*)Plo + off) = make_uint4(L[0], L[1], L[2], L[3]);
            __syncwarp();
        }

        // ---- O += P @ V  (warp reads only its own P rows) ----
#pragma unroll
        for (int kk2 = 0; kk2 < 8; kk2++) {
            wmma::fragment<wmma::matrix_a, 16, 16, 16, __nv_bfloat16, wmma::row_major> ph, pl;
            wmma::load_matrix_sync(ph, Phi + wid * 16 * PP + kk2 * 16, PP);
            wmma::load_matrix_sync(pl, Plo + wid * 16 * PP + kk2 * 16, PP);
#pragma unroll
            for (int db = 0; db < 4; db++) {
                wmma::fragment<wmma::matrix_b, 16, 16, 16, __nv_bfloat16, wmma::row_major> vh, vl;
                wmma::load_matrix_sync(vh, Vhi + kk2 * 16 * PQK + db * 16, PQK);
                wmma::load_matrix_sync(vl, Vlo + kk2 * 16 * PQK + db * 16, PQK);
                wmma::mma_sync(oacc[db], ph, vh, oacc[db]);
                wmma::mma_sync(oacc[db], ph, vl, oacc[db]);
                wmma::mma_sync(oacc[db], pl, vh, oacc[db]);
            }
        }
    }

    // ---- epilogue: row sums, normalize, store ----
    float lpair = lsum + __shfl_xor_sync(0xffffffffu, lsum, 1);
    if (cw == 0) lred[qrow] = lpair;
    __syncthreads();
    const float inv = 1.0f / lred[qrow];

    float* dst = g_ao + (size_t)(n * S_LEN + q0 + qrow) * EMB + h * HD;
#pragma unroll
    for (int db = 0; db < 4; db++) {
        wmma::store_matrix_sync(scr, oacc[db], PSCR, wmma::mem_row_major);
        __syncwarp();
        float4 o0, o1;
        const float* s = scr + r * PSCR + cw * 8;
        o0.x = s[0] * inv; o0.y = s[1] * inv; o0.z = s[2] * inv; o0.w = s[3] * inv;
        o1.x = s[4] * inv; o1.y = s[5] * inv; o1.z = s[6] * inv; o1.w = s[7] * inv;
        *(float4*)(dst + db * 16 + cw * 8)     = o0;
        *(float4*)(dst + db * 16 + cw * 8 + 4) = o1;
        __syncwarp();
    }
}

// ---------------------------------------------------------------------------
// Kernel 3: output projection via wmma bf16 hi/lo: out = g_ao @ Wo^T + bo
// grid (EMB/128, 8192/128), 256 threads. CTA tile 128x128, warp tile 32x64.
// ---------------------------------------------------------------------------
#define PK 24   // bf16 pitch for 16-wide k chunks

__global__ __launch_bounds__(256)
void out_wmma_kernel(const float* __restrict__ Wo, const float* __restrict__ bo,
                     float* __restrict__ out)
{
    __shared__ __nv_bfloat16 Ahi[128 * PK], Alo[128 * PK];
    __shared__ __nv_bfloat16 Bhi[128 * PK], Blo[128 * PK];
    __shared__ float scrs[8 * 16 * PSCR];

    const int tid = threadIdx.x, wid = tid >> 5, lane = tid & 31;
    const int r0 = blockIdx.y * 128;
    const int e0 = blockIdx.x * 128;
    const int wr = wid & 3;    // row group (32 rows)
    const int wc = wid >> 2;   // col group (64 cols)
    float* scr = scrs + wid * (16 * PSCR);

    wmma::fragment<wmma::accumulator, 16, 16, 16, float> acc[2][4];
#pragma unroll
    for (int i = 0; i < 2; i++)
#pragma unroll
        for (int j = 0; j < 4; j++) wmma::fill_fragment(acc[i][j], 0.0f);

    const int sr   = tid >> 1;   // staging row 0..127
    const int sh   = tid & 1;    // 8-col half of 16

    for (int c0 = 0; c0 < EMB; c0 += 16) {
        __syncthreads();
        {
            const float4* a4 = (const float4*)(g_ao + (size_t)(r0 + sr) * EMB + c0) + sh * 2;
            const float4* b4 = (const float4*)(Wo  + (size_t)(e0 + sr) * EMB + c0) + sh * 2;
            float4 a0 = a4[0], a1 = a4[1];
            float4 b0 = b4[0], b1 = b4[1];
            float fa[8] = {a0.x, a0.y, a0.z, a0.w, a1.x, a1.y, a1.z, a1.w};
            float fb[8] = {b0.x, b0.y, b0.z, b0.w, b1.x, b1.y, b1.z, b1.w};
            uint32_t H[4], L[4];
#pragma unroll
            for (int u = 0; u < 4; u++) split2(fa[2 * u], fa[2 * u + 1], H[u], L[u]);
            uint32_t off = (uint32_t)(sr * (PK * 2) + sh * 16);
            *(uint4*)((char*)Ahi + off) = make_uint4(H[0], H[1], H[2], H[3]);
            *(uint4*)((char*)Alo + off) = make_uint4(L[0], L[1], L[2], L[3]);
#pragma unroll
            for (int u = 0; u < 4; u++) split2(fb[2 * u], fb[2 * u + 1], H[u], L[u]);
            *(uint4*)((char*)Bhi + off) = make_uint4(H[0], H[1], H[2], H[3]);
            *(uint4*)((char*)Blo + off) = make_uint4(L[0], L[1], L[2], L[3]);
        }
        __syncthreads();

        wmma::fragment<wmma::matrix_a, 16, 16, 16, __nv_bfloat16, wmma::row_major> ah[2], al[2];
#pragma unroll
        for (int i = 0; i < 2; i++) {
            wmma::load_matrix_sync(ah[i], Ahi + (wr * 32 + i * 16) * PK, PK);
            wmma::load_matrix_sync(al[i], Alo + (wr * 32 + i * 16) * PK, PK);
        }
#pragma unroll
        for (int j = 0; j < 4; j++) {
            wmma::fragment<wmma::matrix_b, 16, 16, 16, __nv_bfloat16, wmma::col_major> bh, bl;
            wmma::load_matrix_sync(bh, Bhi + (wc * 64 + j * 16) * PK, PK);
            wmma::load_matrix_sync(bl, Blo + (wc * 64 + j * 16) * PK, PK);
#pragma unroll
            for (int i = 0; i < 2; i++) {
                wmma::mma_sync(acc[i][j], ah[i], bh, acc[i][j]);
                wmma::mma_sync(acc[i][j], ah[i], bl, acc[i][j]);
                wmma::mma_sync(acc[i][j], al[i], bh, acc[i][j]);
            }
        }
    }

    // epilogue: + bias, store
    const int r = lane >> 1, cw = lane & 1;
#pragma unroll
    for (int i = 0; i < 2; i++)
#pragma unroll
        for (int j = 0; j < 4; j++) {
            wmma::store_matrix_sync(scr, acc[i][j], PSCR, wmma::mem_row_major);
            __syncwarp();
            const int row = r0 + wr * 32 + i * 16 + r;
            const int col = e0 + wc * 64 + j * 16 + cw * 8;
            const float4 bv0 = *(const float4*)(bo + col);
            const float4 bv1 = *(const float4*)(bo + col + 4);
            const float* s = scr + r * PSCR + cw * 8;
            float4 o0, o1;
            o0.x = s[0] + bv0.x; o0.y = s[1] + bv0.y; o0.z = s[2] + bv0.z; o0.w = s[3] + bv0.w;
            o1.x = s[4] + bv1.x; o1.y = s[5] + bv1.y; o1.z = s[6] + bv1.z; o1.w = s[7] + bv1.w;
            *(float4*)(out + (size_t)row * EMB + col)     = o0;
            *(float4*)(out + (size_t)row * EMB + col + 4) = o1;
            __syncwarp();
        }
}

// ---------------------------------------------------------------------------
extern "C" void kernel_launch(void* const* d_in, const int* in_sizes, int n_in,
                              void* d_out, int out_size)
{
    const float* values  = (const float*)d_in[0];
    const float* queries = (const float*)d_in[1];
    const float* keys    = (const float*)d_in[2];
    const int*   mask    = (const int*)  d_in[3];
    const float* Wv      = (const float*)d_in[4];
    const float* Wk      = (const float*)d_in[5];
    const float* Wq      = (const float*)d_in[6];
    const float* Wo      = (const float*)d_in[7];
    const float* bo      = (const float*)d_in[8];
    float* out = (float*)d_out;

    static bool attr_set = false;
    if (!attr_set) {
        cudaFuncSetAttribute(attn_wmma_kernel,
                             cudaFuncAttributeMaxDynamicSharedMemorySize,
                             ATTN_SMEM_BYTES);
        attr_set = true;
    }

    mask_pack_kernel<<<(N_B * S_LEN * MWORDS * 32) / 256, 256>>>(mask);

    dim3 pgrid(S_LEN / 32, N_B * HEADS, 3);
    proj_kernel<<<pgrid, 256>>>(queries, keys, values, Wq, Wk, Wv);

    dim3 agrid(HEADS, S_LEN / 128, N_B);
    attn_wmma_kernel<<<agrid, 256, ATTN_SMEM_BYTES>>>();

    dim3 ggrid(EMB / 128, (N_B * S_LEN) / 128);
    out_wmma_kernel<<<ggrid, 256>>>(Wo, bo, out);
}

// round 5
// speedup vs baseline: 1.9874x; 1.1521x over previous
#include <cuda_runtime.h>
#include <cuda_bf16.h>
#include <mma.h>
#include <cstdint>

using namespace nvcuda;

#define N_B    4
#define S_LEN  2048
#define EMB    1024
#define HEADS  16
#define HD     64
#define MWORDS (S_LEN / 32)

#define PT   72    // bf16 pitch (rows of 64 bf16 + 8 pad)
#define PSCR 20    // float pitch for scratch

// ---------------- scratch (device globals) ---------------------------------
__device__ float g_q[N_B * HEADS * S_LEN * HD];
__device__ float g_k[N_B * HEADS * S_LEN * HD];
__device__ float g_v[N_B * HEADS * S_LEN * HD];
__device__ float g_ao[N_B * S_LEN * EMB];
__device__ unsigned g_mbits[N_B * S_LEN * MWORDS];

__device__ __forceinline__ void split2(float x0, float x1, uint32_t& hi, uint32_t& lo) {
    __nv_bfloat16 h0 = __float2bfloat16_rn(x0), h1 = __float2bfloat16_rn(x1);
    float r0 = x0 - __bfloat162float(h0), r1 = x1 - __bfloat162float(h1);
    __nv_bfloat16 l0 = __float2bfloat16_rn(r0), l1 = __float2bfloat16_rn(r1);
    __nv_bfloat162 hp; hp.x = h0; hp.y = h1;
    __nv_bfloat162 lp; lp.x = l0; lp.y = l1;
    hi = *reinterpret_cast<uint32_t*>(&hp);
    lo = *reinterpret_cast<uint32_t*>(&lp);
}

// stage nrows x 64 f32 (row stride `stride` floats) -> bf16 hi/lo smem pitch PT
// t in [0, 2*nrows): r = t>>1, half = t&1 (32 cols per thread)
__device__ __forceinline__ void stage_rows(const float* __restrict__ src, size_t stride,
                                           char* s_hi, char* s_lo, int t)
{
    const int r    = t >> 1;
    const int half = t & 1;
    const float4* s4 = (const float4*)(src + (size_t)r * stride) + half * 8;
#pragma unroll
    for (int tt = 0; tt < 4; tt++) {
        float4 a = s4[2 * tt], b = s4[2 * tt + 1];
        float f[8] = {a.x, a.y, a.z, a.w, b.x, b.y, b.z, b.w};
        uint32_t H[4], L[4];
#pragma unroll
        for (int u = 0; u < 4; u++) split2(f[2 * u], f[2 * u + 1], H[u], L[u]);
        uint32_t off = (uint32_t)(r * (PT * 2) + half * 64 + tt * 16);
        *(uint4*)(s_hi + off) = make_uint4(H[0], H[1], H[2], H[3]);
        *(uint4*)(s_lo + off) = make_uint4(L[0], L[1], L[2], L[3]);
    }
}

// ---------------------------------------------------------------------------
// Kernel 0: pack mask bits
// ---------------------------------------------------------------------------
__global__ __launch_bounds__(256)
void mask_pack_kernel(const int* __restrict__ mask)
{
    int gid  = blockIdx.x * 256 + threadIdx.x;
    int w    = gid >> 5;
    int lane = gid & 31;
    int v = mask[(size_t)w * 32 + lane];
    unsigned bits = __ballot_sync(0xffffffffu, v != 0);
    if (lane == 0) g_mbits[w] = bits;
}

// ---------------------------------------------------------------------------
// Kernel 1: projections via wmma bf16 hi/lo.  y = x_head @ W^T
// grid (S/128, N_B*HEADS, 3), 256 threads. CTA: 128 rows x 64 cols, K=64.
// ---------------------------------------------------------------------------
#define PJ_WHI 0
#define PJ_WLO 9216
#define PJ_XHI 18432
#define PJ_XLO 36864
#define PJ_SCR 55296
#define PJ_SMEM (55296 + 10240)

__global__ __launch_bounds__(256, 2)
void proj_wmma_kernel(const float* __restrict__ xq, const float* __restrict__ xk,
                      const float* __restrict__ xv,
                      const float* __restrict__ Wq, const float* __restrict__ Wk,
                      const float* __restrict__ Wv)
{
    extern __shared__ char sm[];
    __nv_bfloat16* Whi = (__nv_bfloat16*)(sm + PJ_WHI);
    __nv_bfloat16* Wlo = (__nv_bfloat16*)(sm + PJ_WLO);
    __nv_bfloat16* Xhi = (__nv_bfloat16*)(sm + PJ_XHI);
    __nv_bfloat16* Xlo = (__nv_bfloat16*)(sm + PJ_XLO);

    const int which = blockIdx.z;
    const float* X; const float* W; float* Y;
    if (which == 0)      { X = xq; W = Wq; Y = g_q; }
    else if (which == 1) { X = xk; W = Wk; Y = g_k; }
    else                 { X = xv; W = Wv; Y = g_v; }

    const int nh = blockIdx.y;
    const int n  = nh / HEADS;
    const int h  = nh % HEADS;
    const int s0 = blockIdx.x * 128;
    const int tid = threadIdx.x, wid = tid >> 5, lane = tid & 31;
    float* scr = (float*)(sm + PJ_SCR) + wid * (16 * PSCR);

    // stage X (128x64) and W (64x64)
    stage_rows(X + (size_t)(n * S_LEN + s0) * EMB + h * HD, EMB,
               (char*)Xhi, (char*)Xlo, tid);
    if (tid < 128)
        stage_rows(W, HD, (char*)Whi, (char*)Wlo, tid);
    __syncthreads();

    wmma::fragment<wmma::accumulator, 16, 16, 16, float> acc[4];
#pragma unroll
    for (int j = 0; j < 4; j++) wmma::fill_fragment(acc[j], 0.0f);

#pragma unroll
    for (int kk = 0; kk < 4; kk++) {
        wmma::fragment<wmma::matrix_a, 16, 16, 16, __nv_bfloat16, wmma::row_major> ah, al;
        wmma::load_matrix_sync(ah, Xhi + wid * 16 * PT + kk * 16, PT);
        wmma::load_matrix_sync(al, Xlo + wid * 16 * PT + kk * 16, PT);
#pragma unroll
        for (int j = 0; j < 4; j++) {
            wmma::fragment<wmma::matrix_b, 16, 16, 16, __nv_bfloat16, wmma::col_major> bh, bl;
            wmma::load_matrix_sync(bh, Whi + j * 16 * PT + kk * 16, PT);
            wmma::load_matrix_sync(bl, Wlo + j * 16 * PT + kk * 16, PT);
            wmma::mma_sync(acc[j], ah, bh, acc[j]);
            wmma::mma_sync(acc[j], ah, bl, acc[j]);
            wmma::mma_sync(acc[j], al, bh, acc[j]);
        }
    }

    const int r = lane >> 1, cw = lane & 1;
    float* Yb = Y + (size_t)((n * HEADS + h) * S_LEN + s0 + wid * 16) * HD;
#pragma unroll
    for (int j = 0; j < 4; j++) {
        wmma::store_matrix_sync(scr, acc[j], PSCR, wmma::mem_row_major);
        __syncwarp();
        const float* s = scr + r * PSCR + cw * 8;
        float4 o0 = make_float4(s[0], s[1], s[2], s[3]);
        float4 o1 = make_float4(s[4], s[5], s[6], s[7]);
        *(float4*)(Yb + (size_t)r * HD + j * 16 + cw * 8)     = o0;
        *(float4*)(Yb + (size_t)r * HD + j * 16 + cw * 8 + 4) = o1;
        __syncwarp();
    }
}

// ---------------------------------------------------------------------------
// Kernel 2: wmma flash attention, kv-tile 64, Q fragments in registers
// grid (HEADS, S_LEN/128, N_B), 256 threads (8 warps x 16 q-rows)
// smem 84.5KB -> 2 CTAs/SM
// ---------------------------------------------------------------------------
#define A_KHI  0
#define A_KLO  9216
#define A_VHI  18432
#define A_VLO  27648
#define A_PHI  36864
#define A_PLO  55296
#define A_SCR  73728
#define A_LRED 83968
#define ATTN_SMEM (83968 + 512)

__global__ __launch_bounds__(256, 2)
void attn_wmma_kernel()
{
    extern __shared__ char sm[];
    __nv_bfloat16* Khi = (__nv_bfloat16*)(sm + A_KHI);
    __nv_bfloat16* Klo = (__nv_bfloat16*)(sm + A_KLO);
    __nv_bfloat16* Vhi = (__nv_bfloat16*)(sm + A_VHI);
    __nv_bfloat16* Vlo = (__nv_bfloat16*)(sm + A_VLO);
    __nv_bfloat16* Phi = (__nv_bfloat16*)(sm + A_PHI);
    __nv_bfloat16* Plo = (__nv_bfloat16*)(sm + A_PLO);
    float*         lred = (float*)(sm + A_LRED);

    const int tid = threadIdx.x, wid = tid >> 5, lane = tid & 31;
    const int h = blockIdx.x, qt = blockIdx.y, n = blockIdx.z;
    const int q0 = qt * 128;
    float* scr = (float*)(sm + A_SCR) + wid * (16 * PSCR);

    const float* Qg = g_q + (size_t)(n * HEADS + h) * S_LEN * HD + (size_t)q0 * HD;
    const float* Kg = g_k + (size_t)(n * HEADS + h) * S_LEN * HD;
    const float* Vg = g_v + (size_t)(n * HEADS + h) * S_LEN * HD;

    // ---- stage Q through the (not yet used) P region, hoist fragments ----
    stage_rows(Qg, HD, (char*)Phi, (char*)Plo, tid);
    __syncthreads();

    wmma::fragment<wmma::matrix_a, 16, 16, 16, __nv_bfloat16, wmma::row_major> qh[4], ql[4];
#pragma unroll
    for (int kk = 0; kk < 4; kk++) {
        wmma::load_matrix_sync(qh[kk], Phi + wid * 16 * PT + kk * 16, PT);
        wmma::load_matrix_sync(ql[kk], Plo + wid * 16 * PT + kk * 16, PT);
    }

    const int r  = lane >> 1;
    const int cw = lane & 1;
    const int qrow = wid * 16 + r;
    const unsigned* mrow = g_mbits + (size_t)(n * S_LEN + q0 + qrow) * MWORDS;

    wmma::fragment<wmma::accumulator, 16, 16, 16, float> oacc[4];
#pragma unroll
    for (int db = 0; db < 4; db++) wmma::fill_fragment(oacc[db], 0.0f);
    float lsum = 0.f;

    for (int it = 0; it < S_LEN / 64; it++) {
        const int k0 = it * 64;
        __syncthreads();   // prev iter's V reads done; Q frags loaded (it=0)
        if (tid < 128) stage_rows(Kg + (size_t)k0 * HD, HD, (char*)Khi, (char*)Klo, tid);
        else           stage_rows(Vg + (size_t)k0 * HD, HD, (char*)Vhi, (char*)Vlo, tid - 128);
        __syncthreads();

        // ---- S = QK^T, this warp's 16 rows x 64 k-cols (4 nb blocks) ----
#pragma unroll
        for (int nb = 0; nb < 4; nb++) {
            wmma::fragment<wmma::accumulator, 16, 16, 16, float> sacc;
            wmma::fill_fragment(sacc, 0.0f);
#pragma unroll
            for (int kk = 0; kk < 4; kk++) {
                wmma::fragment<wmma::matrix_b, 16, 16, 16, __nv_bfloat16, wmma::col_major> bh, bl;
                wmma::load_matrix_sync(bh, Khi + nb * 16 * PT + kk * 16, PT);
                wmma::load_matrix_sync(bl, Klo + nb * 16 * PT + kk * 16, PT);
                wmma::mma_sync(sacc, qh[kk], bh, sacc);
                wmma::mma_sync(sacc, qh[kk], bl, sacc);
                wmma::mma_sync(sacc, ql[kk], bh, sacc);
            }
            wmma::store_matrix_sync(scr, sacc, PSCR, wmma::mem_row_major);
            __syncwarp();

            unsigned word = mrow[it * 2 + (nb >> 1)];
            int shift = ((nb & 1) << 4) + (cw << 3);
            float p[8];
#pragma unroll
            for (int j = 0; j < 8; j++) {
                float e = __expf(scr[r * PSCR + cw * 8 + j] * 0.03125f);
                p[j] = ((word >> (shift + j)) & 1u) ? e : 0.f;
                lsum += p[j];
            }
            uint32_t H[4], L[4];
#pragma unroll
            for (int u = 0; u < 4; u++) split2(p[2 * u], p[2 * u + 1], H[u], L[u]);
            uint32_t off = (uint32_t)(qrow * (PT * 2) + nb * 32 + cw * 16);
            *(uint4*)((char*)Phi + off) = make_uint4(H[0], H[1], H[2], H[3]);
            *(uint4*)((char*)Plo + off) = make_uint4(L[0], L[1], L[2], L[3]);
            __syncwarp();
        }

        // ---- O += P @ V (warp-private P rows; V staged this iter) ----
#pragma unroll
        for (int kk2 = 0; kk2 < 4; kk2++) {
            wmma::fragment<wmma::matrix_a, 16, 16, 16, __nv_bfloat16, wmma::row_major> ph, pl;
            wmma::load_matrix_sync(ph, Phi + wid * 16 * PT + kk2 * 16, PT);
            wmma::load_matrix_sync(pl, Plo + wid * 16 * PT + kk2 * 16, PT);
#pragma unroll
            for (int db = 0; db < 4; db++) {
                wmma::fragment<wmma::matrix_b, 16, 16, 16, __nv_bfloat16, wmma::row_major> vh, vl;
                wmma::load_matrix_sync(vh, Vhi + kk2 * 16 * PT + db * 16, PT);
                wmma::load_matrix_sync(vl, Vlo + kk2 * 16 * PT + db * 16, PT);
                wmma::mma_sync(oacc[db], ph, vh, oacc[db]);
                wmma::mma_sync(oacc[db], ph, vl, oacc[db]);
                wmma::mma_sync(oacc[db], pl, vh, oacc[db]);
            }
        }
    }

    // ---- epilogue ----
    float lpair = lsum + __shfl_xor_sync(0xffffffffu, lsum, 1);
    if (cw == 0) lred[qrow] = lpair;
    __syncthreads();
    const float inv = 1.0f / lred[qrow];

    float* dst = g_ao + (size_t)(n * S_LEN + q0 + qrow) * EMB + h * HD;
#pragma unroll
    for (int db = 0; db < 4; db++) {
        wmma::store_matrix_sync(scr, oacc[db], PSCR, wmma::mem_row_major);
        __syncwarp();
        const float* s = scr + r * PSCR + cw * 8;
        float4 o0 = make_float4(s[0] * inv, s[1] * inv, s[2] * inv, s[3] * inv);
        float4 o1 = make_float4(s[4] * inv, s[5] * inv, s[6] * inv, s[7] * inv);
        *(float4*)(dst + db * 16 + cw * 8)     = o0;
        *(float4*)(dst + db * 16 + cw * 8 + 4) = o1;
        __syncwarp();
    }
}

// ---------------------------------------------------------------------------
// Kernel 3: output projection, BK=64
// grid (EMB/128, 8192/128), 256 threads. CTA tile 128x128, warp 32x64.
// ---------------------------------------------------------------------------
#define O_AHI 0
#define O_ALO 18432
#define O_BHI 36864
#define O_BLO 55296
#define O_SCR 73728
#define OUT_SMEM (73728 + 10240)

__global__ __launch_bounds__(256, 2)
void out_wmma_kernel(const float* __restrict__ Wo, const float* __restrict__ bo,
                     float* __restrict__ out)
{
    extern __shared__ char sm[];
    __nv_bfloat16* Ahi = (__nv_bfloat16*)(sm + O_AHI);
    __nv_bfloat16* Alo = (__nv_bfloat16*)(sm + O_ALO);
    __nv_bfloat16* Bhi = (__nv_bfloat16*)(sm + O_BHI);
    __nv_bfloat16* Blo = (__nv_bfloat16*)(sm + O_BLO);

    const int tid = threadIdx.x, wid = tid >> 5, lane = tid & 31;
    const int r0 = blockIdx.y * 128;
    const int e0 = blockIdx.x * 128;
    const int wr = wid & 3;
    const int wc = wid >> 2;
    float* scr = (float*)(sm + O_SCR) + wid * (16 * PSCR);

    wmma::fragment<wmma::accumulator, 16, 16, 16, float> acc[2][4];
#pragma unroll
    for (int i = 0; i < 2; i++)
#pragma unroll
        for (int j = 0; j < 4; j++) wmma::fill_fragment(acc[i][j], 0.0f);

    for (int c0 = 0; c0 < EMB; c0 += 64) {
        __syncthreads();
        stage_rows(g_ao + (size_t)r0 * EMB + c0, EMB, (char*)Ahi, (char*)Alo, tid);
        stage_rows(Wo  + (size_t)e0 * EMB + c0, EMB, (char*)Bhi, (char*)Blo, tid);
        __syncthreads();

#pragma unroll
        for (int kk = 0; kk < 4; kk++) {
            wmma::fragment<wmma::matrix_a, 16, 16, 16, __nv_bfloat16, wmma::row_major> ah[2], al[2];
#pragma unroll
            for (int i = 0; i < 2; i++) {
                wmma::load_matrix_sync(ah[i], Ahi + (wr * 32 + i * 16) * PT + kk * 16, PT);
                wmma::load_matrix_sync(al[i], Alo + (wr * 32 + i * 16) * PT + kk * 16, PT);
            }
#pragma unroll
            for (int j = 0; j < 4; j++) {
                wmma::fragment<wmma::matrix_b, 16, 16, 16, __nv_bfloat16, wmma::col_major> bh, bl;
                wmma::load_matrix_sync(bh, Bhi + (wc * 64 + j * 16) * PT + kk * 16, PT);
                wmma::load_matrix_sync(bl, Blo + (wc * 64 + j * 16) * PT + kk * 16, PT);
#pragma unroll
                for (int i = 0; i < 2; i++) {
                    wmma::mma_sync(acc[i][j], ah[i], bh, acc[i][j]);
                    wmma::mma_sync(acc[i][j], ah[i], bl, acc[i][j]);
                    wmma::mma_sync(acc[i][j], al[i], bh, acc[i][j]);
                }
            }
        }
    }

    const int r = lane >> 1, cw = lane & 1;
#pragma unroll
    for (int i = 0; i < 2; i++)
#pragma unroll
        for (int j = 0; j < 4; j++) {
            wmma::store_matrix_sync(scr, acc[i][j], PSCR, wmma::mem_row_major);
            __syncwarp();
            const int row = r0 + wr * 32 + i * 16 + r;
            const int col = e0 + wc * 64 + j * 16 + cw * 8;
            const float4 bv0 = *(const float4*)(bo + col);
            const float4 bv1 = *(const float4*)(bo + col + 4);
            const float* s = scr + r * PSCR + cw * 8;
            float4 o0 = make_float4(s[0] + bv0.x, s[1] + bv0.y, s[2] + bv0.z, s[3] + bv0.w);
            float4 o1 = make_float4(s[4] + bv1.x, s[5] + bv1.y, s[6] + bv1.z, s[7] + bv1.w);
            *(float4*)(out + (size_t)row * EMB + col)     = o0;
            *(float4*)(out + (size_t)row * EMB + col + 4) = o1;
            __syncwarp();
        }
}

// ---------------------------------------------------------------------------
extern "C" void kernel_launch(void* const* d_in, const int* in_sizes, int n_in,
                              void* d_out, int out_size)
{
    const float* values  = (const float*)d_in[0];
    const float* queries = (const float*)d_in[1];
    const float* keys    = (const float*)d_in[2];
    const int*   mask    = (const int*)  d_in[3];
    const float* Wv      = (const float*)d_in[4];
    const float* Wk      = (const float*)d_in[5];
    const float* Wq      = (const float*)d_in[6];
    const float* Wo      = (const float*)d_in[7];
    const float* bo      = (const float*)d_in[8];
    float* out = (float*)d_out;

    static bool attr_set = false;
    if (!attr_set) {
        cudaFuncSetAttribute(proj_wmma_kernel,
                             cudaFuncAttributeMaxDynamicSharedMemorySize, PJ_SMEM);
        cudaFuncSetAttribute(attn_wmma_kernel,
                             cudaFuncAttributeMaxDynamicSharedMemorySize, ATTN_SMEM);
        cudaFuncSetAttribute(out_wmma_kernel,
                             cudaFuncAttributeMaxDynamicSharedMemorySize, OUT_SMEM);
        attr_set = true;
    }

    mask_pack_kernel<<<(N_B * S_LEN * MWORDS * 32) / 256, 256>>>(mask);

    dim3 pgrid(S_LEN / 128, N_B * HEADS, 3);
    proj_wmma_kernel<<<pgrid, 256, PJ_SMEM>>>(queries, keys, values, Wq, Wk, Wv);

    dim3 agrid(HEADS, S_LEN / 128, N_B);
    attn_wmma_kernel<<<agrid, 256, ATTN_SMEM>>>();

    dim3 ggrid(EMB / 128, (N_B * S_LEN) / 128);
    out_wmma_kernel<<<ggrid, 256, OUT_SMEM>>>(Wo, bo, out);
}

// round 6
// speedup vs baseline: 3.1494x; 1.5847x over previous
#include <cuda_runtime.h>
#include <cuda_bf16.h>
#include <mma.h>
#include <cstdint>

using namespace nvcuda;

#define N_B    4
#define S_LEN  2048
#define EMB    1024
#define HEADS  16
#define HD     64
#define MWORDS (S_LEN / 32)

#define PT   72    // bf16 pitch (row = 144 bytes) — conflict-free for ldmatrix
#define PSCR 20    // float pitch for wmma scratch

// ---------------- scratch (device globals) ---------------------------------
__device__ float g_q[N_B * HEADS * S_LEN * HD];
__device__ float g_k[N_B * HEADS * S_LEN * HD];
__device__ float g_v[N_B * HEADS * S_LEN * HD];
__device__ float g_ao[N_B * S_LEN * EMB];
__device__ unsigned g_mbits[N_B * S_LEN * MWORDS];

__device__ __forceinline__ void split2(float x0, float x1, uint32_t& hi, uint32_t& lo) {
    __nv_bfloat16 h0 = __float2bfloat16_rn(x0), h1 = __float2bfloat16_rn(x1);
    float r0 = x0 - __bfloat162float(h0), r1 = x1 - __bfloat162float(h1);
    __nv_bfloat16 l0 = __float2bfloat16_rn(r0), l1 = __float2bfloat16_rn(r1);
    __nv_bfloat162 hp; hp.x = h0; hp.y = h1;
    __nv_bfloat162 lp; lp.x = l0; lp.y = l1;
    hi = *reinterpret_cast<uint32_t*>(&hp);
    lo = *reinterpret_cast<uint32_t*>(&lp);
}

__device__ __forceinline__ uint32_t smem_u32(const void* p) {
    uint32_t a;
    asm("{ .reg .u64 t; cvta.to.shared.u64 t, %1; cvt.u32.u64 %0, t; }"
        : "=r"(a) : "l"(p));
    return a;
}

// ---- raw tensor-core primitives (sm_80-compatible, no 'a' target needed) ---
__device__ __forceinline__ void ldsm_x4(uint32_t* r, uint32_t addr) {
    asm volatile("ldmatrix.sync.aligned.m8n8.x4.shared.b16 {%0,%1,%2,%3}, [%4];"
                 : "=r"(r[0]), "=r"(r[1]), "=r"(r[2]), "=r"(r[3]) : "r"(addr));
}
__device__ __forceinline__ void ldsm_x2(uint32_t* r, uint32_t addr) {
    asm volatile("ldmatrix.sync.aligned.m8n8.x2.shared.b16 {%0,%1}, [%2];"
                 : "=r"(r[0]), "=r"(r[1]) : "r"(addr));
}
__device__ __forceinline__ void ldsm_x2_t(uint32_t* r, uint32_t addr) {
    asm volatile("ldmatrix.sync.aligned.m8n8.x2.trans.shared.b16 {%0,%1}, [%2];"
                 : "=r"(r[0]), "=r"(r[1]) : "r"(addr));
}
__device__ __forceinline__ void mma16816(float* d, const uint32_t* a, const uint32_t* b) {
    asm volatile(
        "mma.sync.aligned.m16n8k16.row.col.f32.bf16.bf16.f32 "
        "{%0,%1,%2,%3}, {%4,%5,%6,%7}, {%8,%9}, {%0,%1,%2,%3};"
        : "+f"(d[0]), "+f"(d[1]), "+f"(d[2]), "+f"(d[3])
        : "r"(a[0]), "r"(a[1]), "r"(a[2]), "r"(a[3]), "r"(b[0]), "r"(b[1]));
}

// stage nrows x 64 f32 (row stride `stride`) -> bf16 hi/lo smem pitch PT
// t in [0, 2*nrows): r = t>>1, half = t&1 (32 cols)
__device__ __forceinline__ void stage_rows(const float* __restrict__ src, size_t stride,
                                           char* s_hi, char* s_lo, int t)
{
    const int r    = t >> 1;
    const int half = t & 1;
    const float4* s4 = (const float4*)(src + (size_t)r * stride) + half * 8;
#pragma unroll
    for (int tt = 0; tt < 4; tt++) {
        float4 a = s4[2 * tt], b = s4[2 * tt + 1];
        float f[8] = {a.x, a.y, a.z, a.w, b.x, b.y, b.z, b.w};
        uint32_t H[4], L[4];
#pragma unroll
        for (int u = 0; u < 4; u++) split2(f[2 * u], f[2 * u + 1], H[u], L[u]);
        uint32_t off = (uint32_t)(r * (PT * 2) + half * 64 + tt * 16);
        *(uint4*)(s_hi + off) = make_uint4(H[0], H[1], H[2], H[3]);
        *(uint4*)(s_lo + off) = make_uint4(L[0], L[1], L[2], L[3]);
    }
}

// stage 32 x 64 f32 tile: t in [0,256): r = t>>3, oct = t&7 (8 cols)
__device__ __forceinline__ void stage32(const float* __restrict__ src,
                                        char* s_hi, char* s_lo, int t)
{
    const int r   = t >> 3;
    const int oct = t & 7;
    const float4* s4 = (const float4*)(src + (size_t)r * HD) + oct * 2;
    float4 a = s4[0], b = s4[1];
    float f[8] = {a.x, a.y, a.z, a.w, b.x, b.y, b.z, b.w};
    uint32_t H[4], L[4];
#pragma unroll
    for (int u = 0; u < 4; u++) split2(f[2 * u], f[2 * u + 1], H[u], L[u]);
    uint32_t off = (uint32_t)(r * (PT * 2) + oct * 16);
    *(uint4*)(s_hi + off) = make_uint4(H[0], H[1], H[2], H[3]);
    *(uint4*)(s_lo + off) = make_uint4(L[0], L[1], L[2], L[3]);
}

// ---------------------------------------------------------------------------
// Kernel 0: pack mask bits
// ---------------------------------------------------------------------------
__global__ __launch_bounds__(256)
void mask_pack_kernel(const int* __restrict__ mask)
{
    int gid  = blockIdx.x * 256 + threadIdx.x;
    int w    = gid >> 5;
    int lane = gid & 31;
    int v = mask[(size_t)w * 32 + lane];
    unsigned bits = __ballot_sync(0xffffffffu, v != 0);
    if (lane == 0) g_mbits[w] = bits;
}

// ---------------------------------------------------------------------------
// Kernel 1: projections via wmma bf16 hi/lo (R5 version, kept)
// ---------------------------------------------------------------------------
#define PJ_WHI 0
#define PJ_WLO 9216
#define PJ_XHI 18432
#define PJ_XLO 36864
#define PJ_SCR 55296
#define PJ_SMEM (55296 + 10240)

__global__ __launch_bounds__(256, 2)
void proj_wmma_kernel(const float* __restrict__ xq, const float* __restrict__ xk,
                      const float* __restrict__ xv,
                      const float* __restrict__ Wq, const float* __restrict__ Wk,
                      const float* __restrict__ Wv)
{
    extern __shared__ char sm[];
    __nv_bfloat16* Whi = (__nv_bfloat16*)(sm + PJ_WHI);
    __nv_bfloat16* Wlo = (__nv_bfloat16*)(sm + PJ_WLO);
    __nv_bfloat16* Xhi = (__nv_bfloat16*)(sm + PJ_XHI);
    __nv_bfloat16* Xlo = (__nv_bfloat16*)(sm + PJ_XLO);

    const int which = blockIdx.z;
    const float* X; const float* W; float* Y;
    if (which == 0)      { X = xq; W = Wq; Y = g_q; }
    else if (which == 1) { X = xk; W = Wk; Y = g_k; }
    else                 { X = xv; W = Wv; Y = g_v; }

    const int nh = blockIdx.y;
    const int n  = nh / HEADS;
    const int h  = nh % HEADS;
    const int s0 = blockIdx.x * 128;
    const int tid = threadIdx.x, wid = tid >> 5, lane = tid & 31;
    float* scr = (float*)(sm + PJ_SCR) + wid * (16 * PSCR);

    stage_rows(X + (size_t)(n * S_LEN + s0) * EMB + h * HD, EMB,
               (char*)Xhi, (char*)Xlo, tid);
    if (tid < 128)
        stage_rows(W, HD, (char*)Whi, (char*)Wlo, tid);
    __syncthreads();

    wmma::fragment<wmma::accumulator, 16, 16, 16, float> acc[4];
#pragma unroll
    for (int j = 0; j < 4; j++) wmma::fill_fragment(acc[j], 0.0f);

#pragma unroll
    for (int kk = 0; kk < 4; kk++) {
        wmma::fragment<wmma::matrix_a, 16, 16, 16, __nv_bfloat16, wmma::row_major> ah, al;
        wmma::load_matrix_sync(ah, Xhi + wid * 16 * PT + kk * 16, PT);
        wmma::load_matrix_sync(al, Xlo + wid * 16 * PT + kk * 16, PT);
#pragma unroll
        for (int j = 0; j < 4; j++) {
            wmma::fragment<wmma::matrix_b, 16, 16, 16, __nv_bfloat16, wmma::col_major> bh, bl;
            wmma::load_matrix_sync(bh, Whi + j * 16 * PT + kk * 16, PT);
            wmma::load_matrix_sync(bl, Wlo + j * 16 * PT + kk * 16, PT);
            wmma::mma_sync(acc[j], ah, bh, acc[j]);
            wmma::mma_sync(acc[j], ah, bl, acc[j]);
            wmma::mma_sync(acc[j], al, bh, acc[j]);
        }
    }

    const int r = lane >> 1, cw = lane & 1;
    float* Yb = Y + (size_t)((n * HEADS + h) * S_LEN + s0 + wid * 16) * HD;
#pragma unroll
    for (int j = 0; j < 4; j++) {
        wmma::store_matrix_sync(scr, acc[j], PSCR, wmma::mem_row_major);
        __syncwarp();
        const float* s = scr + r * PSCR + cw * 8;
        float4 o0 = make_float4(s[0], s[1], s[2], s[3]);
        float4 o1 = make_float4(s[4], s[5], s[6], s[7]);
        *(float4*)(Yb + (size_t)r * HD + j * 16 + cw * 8)     = o0;
        *(float4*)(Yb + (size_t)r * HD + j * 16 + cw * 8 + 4) = o1;
        __syncwarp();
    }
}

// ---------------------------------------------------------------------------
// Kernel 2: mma.sync flash attention — softmax & P fully in registers
// grid (HEADS, S_LEN/128, N_B), 256 threads (8 warps x 16 q-rows), kv-tile 32
// ---------------------------------------------------------------------------
#define A_QHI  0
#define A_QLO  18432
#define A_KHI  36864
#define A_KLO  41472
#define A_VHI  46080
#define A_VLO  50688
#define ATTN_SMEM (55296 + 256)

__global__ __launch_bounds__(256, 2)
void attn_mma_kernel()
{
    extern __shared__ char sm[];
    const int tid = threadIdx.x, wid = tid >> 5, lane = tid & 31;
    const int h = blockIdx.x, qt = blockIdx.y, n = blockIdx.z;
    const int q0 = qt * 128;

    const float* Qg = g_q + (size_t)(n * HEADS + h) * S_LEN * HD + (size_t)q0 * HD;
    const float* Kg = g_k + (size_t)(n * HEADS + h) * S_LEN * HD;
    const float* Vg = g_v + (size_t)(n * HEADS + h) * S_LEN * HD;

    // ---- stage Q, hoist A-fragments to registers ----
    stage_rows(Qg, HD, sm + A_QHI, sm + A_QLO, tid);
    __syncthreads();

    const int l7  = lane & 7;
    const int s01 = (lane >> 3) & 1;   // row +8 selector for x4/x2
    const int s23 = (lane >> 4) & 1;   // col +16B selector for x4

    uint32_t qh[4][4], ql[4][4];
    {
        uint32_t base = smem_u32(sm) +
                        (uint32_t)((wid * 16 + l7 + s01 * 8) * (PT * 2)) + s23 * 16;
#pragma unroll
        for (int c = 0; c < 4; c++) {
            ldsm_x4(qh[c], base + A_QHI + c * 32);
            ldsm_x4(ql[c], base + A_QLO + c * 32);
        }
    }

    const int g   = lane >> 2;       // row group within warp band
    const int tig = lane & 3;
    const int qrow_g  = q0 + wid * 16 + g;
    const unsigned* mrow0 = g_mbits + (size_t)(n * S_LEN + qrow_g) * MWORDS;
    const unsigned* mrow8 = mrow0 + 8 * MWORDS;

    // ldmatrix source addresses (lane-dependent parts)
    const uint32_t smb = smem_u32(sm);
    const uint32_t kbase = smb + (uint32_t)(l7 * (PT * 2)) + s01 * 16;        // + j*8*144 + c*32
    const uint32_t vbase = smb + (uint32_t)((l7 + 8 * s01) * (PT * 2));       // + c*16*144 + j*16

    float o[8][4];
#pragma unroll
    for (int j = 0; j < 8; j++)
#pragma unroll
        for (int u = 0; u < 4; u++) o[j][u] = 0.f;
    float lsum_g = 0.f, lsum_8 = 0.f;

    const float SC = 0.03125f;

    for (int it = 0; it < S_LEN / 32; it++) {
        __syncthreads();
        stage32(Kg + (size_t)it * 32 * HD, sm + A_KHI, sm + A_KLO, tid);
        stage32(Vg + (size_t)it * 32 * HD, sm + A_VHI, sm + A_VLO, tid);
        __syncthreads();

        // ---- S = Q K^T : 4 n-tiles (8 kv cols each) x 4 k-chunks x 3 ----
        float s[4][4];
#pragma unroll
        for (int j = 0; j < 4; j++)
#pragma unroll
            for (int u = 0; u < 4; u++) s[j][u] = 0.f;

#pragma unroll
        for (int c = 0; c < 4; c++) {
#pragma unroll
            for (int j = 0; j < 4; j++) {
                uint32_t bh[2], bl[2];
                uint32_t ka = kbase + (uint32_t)(j * 8 * (PT * 2)) + c * 32;
                ldsm_x2(bh, ka + A_KHI);
                ldsm_x2(bl, ka + A_KLO);
                mma16816(s[j], qh[c], bh);
                mma16816(s[j], qh[c], bl);
                mma16816(s[j], ql[c], bh);
            }
        }

        // ---- softmax in registers ----
        const unsigned w0 = mrow0[it];
        const unsigned w8 = mrow8[it];
#pragma unroll
        for (int j = 0; j < 4; j++) {
            const int bit = j * 8 + tig * 2;
            float p0 = __expf(s[j][0] * SC);
            float p1 = __expf(s[j][1] * SC);
            float p2 = __expf(s[j][2] * SC);
            float p3 = __expf(s[j][3] * SC);
            p0 = ((w0 >> bit) & 1u)       ? p0 : 0.f;
            p1 = ((w0 >> (bit + 1)) & 1u) ? p1 : 0.f;
            p2 = ((w8 >> bit) & 1u)       ? p2 : 0.f;
            p3 = ((w8 >> (bit + 1)) & 1u) ? p3 : 0.f;
            lsum_g += p0 + p1;
            lsum_8 += p2 + p3;
            s[j][0] = p0; s[j][1] = p1; s[j][2] = p2; s[j][3] = p3;
        }

        // ---- O += P V : accumulator-to-A conversion, P never hits smem ----
#pragma unroll
        for (int c2 = 0; c2 < 2; c2++) {
            uint32_t ah[4], al[4];
            split2(s[2 * c2][0],     s[2 * c2][1],     ah[0], al[0]);
            split2(s[2 * c2][2],     s[2 * c2][3],     ah[1], al[1]);
            split2(s[2 * c2 + 1][0], s[2 * c2 + 1][1], ah[2], al[2]);
            split2(s[2 * c2 + 1][2], s[2 * c2 + 1][3], ah[3], al[3]);
#pragma unroll
            for (int j = 0; j < 8; j++) {
                uint32_t bh[2], bl[2];
                uint32_t va = vbase + (uint32_t)(c2 * 16 * (PT * 2)) + j * 16;
                ldsm_x2_t(bh, va + A_VHI);
                ldsm_x2_t(bl, va + A_VLO);
                mma16816(o[j], ah, bh);
                mma16816(o[j], ah, bl);
                mma16816(o[j], al, bh);
            }
        }
    }

    // ---- epilogue: row sums via shuffle (groups of 4 share a row) ----
    lsum_g += __shfl_xor_sync(0xffffffffu, lsum_g, 1);
    lsum_g += __shfl_xor_sync(0xffffffffu, lsum_g, 2);
    lsum_8 += __shfl_xor_sync(0xffffffffu, lsum_8, 1);
    lsum_8 += __shfl_xor_sync(0xffffffffu, lsum_8, 2);
    const float inv_g = 1.0f / lsum_g;
    const float inv_8 = 1.0f / lsum_8;

    float* dst0 = g_ao + (size_t)(n * S_LEN + qrow_g) * EMB + h * HD;
    float* dst8 = dst0 + (size_t)8 * EMB;
#pragma unroll
    for (int j = 0; j < 8; j++) {
        const int col = j * 8 + tig * 2;
        *(float2*)(dst0 + col) = make_float2(o[j][0] * inv_g, o[j][1] * inv_g);
        *(float2*)(dst8 + col) = make_float2(o[j][2] * inv_8, o[j][3] * inv_8);
    }
}

// ---------------------------------------------------------------------------
// Kernel 3: output projection (R4 version — measured 223us, BK=16 static smem)
// ---------------------------------------------------------------------------
#define PK 24

__global__ __launch_bounds__(256)
void out_wmma_kernel(const float* __restrict__ Wo, const float* __restrict__ bo,
                     float* __restrict__ out)
{
    __shared__ __nv_bfloat16 Ahi[128 * PK], Alo[128 * PK];
    __shared__ __nv_bfloat16 Bhi[128 * PK], Blo[128 * PK];
    __shared__ float scrs[8 * 16 * PSCR];

    const int tid = threadIdx.x, wid = tid >> 5, lane = tid & 31;
    const int r0 = blockIdx.y * 128;
    const int e0 = blockIdx.x * 128;
    const int wr = wid & 3;
    const int wc = wid >> 2;
    float* scr = scrs + wid * (16 * PSCR);

    wmma::fragment<wmma::accumulator, 16, 16, 16, float> acc[2][4];
#pragma unroll
    for (int i = 0; i < 2; i++)
#pragma unroll
        for (int j = 0; j < 4; j++) wmma::fill_fragment(acc[i][j], 0.0f);

    const int sr = tid >> 1;
    const int sh = tid & 1;

    for (int c0 = 0; c0 < EMB; c0 += 16) {
        __syncthreads();
        {
            const float4* a4 = (const float4*)(g_ao + (size_t)(r0 + sr) * EMB + c0) + sh * 2;
            const float4* b4 = (const float4*)(Wo  + (size_t)(e0 + sr) * EMB + c0) + sh * 2;
            float4 a0 = a4[0], a1 = a4[1];
            float4 b0 = b4[0], b1 = b4[1];
            float fa[8] = {a0.x, a0.y, a0.z, a0.w, a1.x, a1.y, a1.z, a1.w};
            float fb[8] = {b0.x, b0.y, b0.z, b0.w, b1.x, b1.y, b1.z, b1.w};
            uint32_t H[4], L[4];
#pragma unroll
            for (int u = 0; u < 4; u++) split2(fa[2 * u], fa[2 * u + 1], H[u], L[u]);
            uint32_t off = (uint32_t)(sr * (PK * 2) + sh * 16);
            *(uint4*)((char*)Ahi + off) = make_uint4(H[0], H[1], H[2], H[3]);
            *(uint4*)((char*)Alo + off) = make_uint4(L[0], L[1], L[2], L[3]);
#pragma unroll
            for (int u = 0; u < 4; u++) split2(fb[2 * u], fb[2 * u + 1], H[u], L[u]);
            *(uint4*)((char*)Bhi + off) = make_uint4(H[0], H[1], H[2], H[3]);
            *(uint4*)((char*)Blo + off) = make_uint4(L[0], L[1], L[2], L[3]);
        }
        __syncthreads();

        wmma::fragment<wmma::matrix_a, 16, 16, 16, __nv_bfloat16, wmma::row_major> ah[2], al[2];
#pragma unroll
        for (int i = 0; i < 2; i++) {
            wmma::load_matrix_sync(ah[i], Ahi + (wr * 32 + i * 16) * PK, PK);
            wmma::load_matrix_sync(al[i], Alo + (wr * 32 + i * 16) * PK, PK);
        }
#pragma unroll
        for (int j = 0; j < 4; j++) {
            wmma::fragment<wmma::matrix_b, 16, 16, 16, __nv_bfloat16, wmma::col_major> bh, bl;
            wmma::load_matrix_sync(bh, Bhi + (wc * 64 + j * 16) * PK, PK);
            wmma::load_matrix_sync(bl, Blo + (wc * 64 + j * 16) * PK, PK);
#pragma unroll
            for (int i = 0; i < 2; i++) {
                wmma::mma_sync(acc[i][j], ah[i], bh, acc[i][j]);
                wmma::mma_sync(acc[i][j], ah[i], bl, acc[i][j]);
                wmma::mma_sync(acc[i][j], al[i], bh, acc[i][j]);
            }
        }
    }

    const int r = lane >> 1, cw = lane & 1;
#pragma unroll
    for (int i = 0; i < 2; i++)
#pragma unroll
        for (int j = 0; j < 4; j++) {
            wmma::store_matrix_sync(scr, acc[i][j], PSCR, wmma::mem_row_major);
            __syncwarp();
            const int row = r0 + wr * 32 + i * 16 + r;
            const int col = e0 + wc * 64 + j * 16 + cw * 8;
            const float4 bv0 = *(const float4*)(bo + col);
            const float4 bv1 = *(const float4*)(bo + col + 4);
            const float* s = scr + r * PSCR + cw * 8;
            float4 o0 = make_float4(s[0] + bv0.x, s[1] + bv0.y, s[2] + bv0.z, s[3] + bv0.w);
            float4 o1 = make_float4(s[4] + bv1.x, s[5] + bv1.y, s[6] + bv1.z, s[7] + bv1.w);
            *(float4*)(out + (size_t)row * EMB + col)     = o0;
            *(float4*)(out + (size_t)row * EMB + col + 4) = o1;
            __syncwarp();
        }
}

// ---------------------------------------------------------------------------
extern "C" void kernel_launch(void* const* d_in, const int* in_sizes, int n_in,
                              void* d_out, int out_size)
{
    const float* values  = (const float*)d_in[0];
    const float* queries = (const float*)d_in[1];
    const float* keys    = (const float*)d_in[2];
    const int*   mask    = (const int*)  d_in[3];
    const float* Wv      = (const float*)d_in[4];
    const float* Wk      = (const float*)d_in[5];
    const float* Wq      = (const float*)d_in[6];
    const float* Wo      = (const float*)d_in[7];
    const float* bo      = (const float*)d_in[8];
    float* out = (float*)d_out;

    static bool attr_set = false;
    if (!attr_set) {
        cudaFuncSetAttribute(proj_wmma_kernel,
                             cudaFuncAttributeMaxDynamicSharedMemorySize, PJ_SMEM);
        cudaFuncSetAttribute(attn_mma_kernel,
                             cudaFuncAttributeMaxDynamicSharedMemorySize, ATTN_SMEM);
        attr_set = true;
    }

    mask_pack_kernel<<<(N_B * S_LEN * MWORDS * 32) / 256, 256>>>(mask);

    dim3 pgrid(S_LEN / 128, N_B * HEADS, 3);
    proj_wmma_kernel<<<pgrid, 256, PJ_SMEM>>>(queries, keys, values, Wq, Wk, Wv);

    dim3 agrid(HEADS, S_LEN / 128, N_B);
    attn_mma_kernel<<<agrid, 256, ATTN_SMEM>>>();

    dim3 ggrid(EMB / 128, (N_B * S_LEN) / 128);
    out_wmma_kernel<<<ggrid, 256>>>(Wo, bo, out);
}

// round 7
// speedup vs baseline: 3.1774x; 1.0089x over previous
#include <cuda_runtime.h>
#include <cuda_bf16.h>
#include <mma.h>
#include <cstdint>

using namespace nvcuda;

#define N_B    4
#define S_LEN  2048
#define EMB    1024
#define HEADS  16
#define HD     64
#define MWORDS (S_LEN / 32)

#define PT   72    // bf16 smem pitch (144 B rows) — conflict-free ldmatrix
#define PSCR 20    // float pitch for wmma scratch

// ---------------- scratch (device globals) ---------------------------------
__device__ __nv_bfloat16 g_qh[N_B * HEADS * S_LEN * HD];
__device__ __nv_bfloat16 g_ql[N_B * HEADS * S_LEN * HD];
__device__ __nv_bfloat16 g_kh[N_B * HEADS * S_LEN * HD];
__device__ __nv_bfloat16 g_kl[N_B * HEADS * S_LEN * HD];
__device__ __nv_bfloat16 g_vh[N_B * HEADS * S_LEN * HD];
__device__ __nv_bfloat16 g_vl[N_B * HEADS * S_LEN * HD];
__device__ __nv_bfloat16 g_aoh[N_B * S_LEN * EMB];
__device__ __nv_bfloat16 g_aol[N_B * S_LEN * EMB];
__device__ __nv_bfloat16 g_woh[EMB * EMB];
__device__ __nv_bfloat16 g_wol[EMB * EMB];
__device__ unsigned g_mbits[N_B * S_LEN * MWORDS];

__device__ __forceinline__ void split2(float x0, float x1, uint32_t& hi, uint32_t& lo) {
    __nv_bfloat16 h0 = __float2bfloat16_rn(x0), h1 = __float2bfloat16_rn(x1);
    float r0 = x0 - __bfloat162float(h0), r1 = x1 - __bfloat162float(h1);
    __nv_bfloat16 l0 = __float2bfloat16_rn(r0), l1 = __float2bfloat16_rn(r1);
    __nv_bfloat162 hp; hp.x = h0; hp.y = h1;
    __nv_bfloat162 lp; lp.x = l0; lp.y = l1;
    hi = *reinterpret_cast<uint32_t*>(&hp);
    lo = *reinterpret_cast<uint32_t*>(&lp);
}

__device__ __forceinline__ uint32_t smem_u32(const void* p) {
    uint32_t a;
    asm("{ .reg .u64 t; cvta.to.shared.u64 t, %1; cvt.u32.u64 %0, t; }"
        : "=r"(a) : "l"(p));
    return a;
}

// ---- raw tensor-core primitives -------------------------------------------
__device__ __forceinline__ void ldsm_x4(uint32_t* r, uint32_t addr) {
    asm volatile("ldmatrix.sync.aligned.m8n8.x4.shared.b16 {%0,%1,%2,%3}, [%4];"
                 : "=r"(r[0]), "=r"(r[1]), "=r"(r[2]), "=r"(r[3]) : "r"(addr));
}
__device__ __forceinline__ void ldsm_x2(uint32_t* r, uint32_t addr) {
    asm volatile("ldmatrix.sync.aligned.m8n8.x2.shared.b16 {%0,%1}, [%2];"
                 : "=r"(r[0]), "=r"(r[1]) : "r"(addr));
}
__device__ __forceinline__ void ldsm_x2_t(uint32_t* r, uint32_t addr) {
    asm volatile("ldmatrix.sync.aligned.m8n8.x2.trans.shared.b16 {%0,%1}, [%2];"
                 : "=r"(r[0]), "=r"(r[1]) : "r"(addr));
}
__device__ __forceinline__ void mma16816(float* d, const uint32_t* a, const uint32_t* b) {
    asm volatile(
        "mma.sync.aligned.m16n8k16.row.col.f32.bf16.bf16.f32 "
        "{%0,%1,%2,%3}, {%4,%5,%6,%7}, {%8,%9}, {%0,%1,%2,%3};"
        : "+f"(d[0]), "+f"(d[1]), "+f"(d[2]), "+f"(d[3])
        : "r"(a[0]), "r"(a[1]), "r"(a[2]), "r"(a[3]), "r"(b[0]), "r"(b[1]));
}

// stage nrows x 64 f32 -> bf16 hi/lo smem pitch PT (used by proj only)
__device__ __forceinline__ void stage_rows_f32(const float* __restrict__ src, size_t stride,
                                               char* s_hi, char* s_lo, int t)
{
    const int r    = t >> 1;
    const int half = t & 1;
    const float4* s4 = (const float4*)(src + (size_t)r * stride) + half * 8;
#pragma unroll
    for (int tt = 0; tt < 4; tt++) {
        float4 a = s4[2 * tt], b = s4[2 * tt + 1];
        float f[8] = {a.x, a.y, a.z, a.w, b.x, b.y, b.z, b.w};
        uint32_t H[4], L[4];
#pragma unroll
        for (int u = 0; u < 4; u++) split2(f[2 * u], f[2 * u + 1], H[u], L[u]);
        uint32_t off = (uint32_t)(r * (PT * 2) + half * 64 + tt * 16);
        *(uint4*)(s_hi + off) = make_uint4(H[0], H[1], H[2], H[3]);
        *(uint4*)(s_lo + off) = make_uint4(L[0], L[1], L[2], L[3]);
    }
}

// ---------------------------------------------------------------------------
// Kernel 0a: pack mask bits
// ---------------------------------------------------------------------------
__global__ __launch_bounds__(256)
void mask_pack_kernel(const int* __restrict__ mask)
{
    int gid  = blockIdx.x * 256 + threadIdx.x;
    int w    = gid >> 5;
    int lane = gid & 31;
    int v = mask[(size_t)w * 32 + lane];
    unsigned bits = __ballot_sync(0xffffffffu, v != 0);
    if (lane == 0) g_mbits[w] = bits;
}

// ---------------------------------------------------------------------------
// Kernel 0b: pre-split Wo into bf16 hi/lo (once)
// ---------------------------------------------------------------------------
__global__ __launch_bounds__(256)
void wo_split_kernel(const float* __restrict__ Wo)
{
    size_t idx = ((size_t)blockIdx.x * 256 + threadIdx.x) * 8;
    float4 a = *(const float4*)(Wo + idx);
    float4 b = *(const float4*)(Wo + idx + 4);
    float f[8] = {a.x, a.y, a.z, a.w, b.x, b.y, b.z, b.w};
    uint32_t H[4], L[4];
#pragma unroll
    for (int u = 0; u < 4; u++) split2(f[2 * u], f[2 * u + 1], H[u], L[u]);
    *(uint4*)(g_woh + idx) = make_uint4(H[0], H[1], H[2], H[3]);
    *(uint4*)(g_wol + idx) = make_uint4(L[0], L[1], L[2], L[3]);
}

// ---------------------------------------------------------------------------
// Kernel 1: projections via wmma bf16 hi/lo, writes pre-split Q/K/V
// grid (S/128, N_B*HEADS, 3), 256 threads
// ---------------------------------------------------------------------------
#define PJ_WHI 0
#define PJ_WLO 9216
#define PJ_XHI 18432
#define PJ_XLO 36864
#define PJ_SCR 55296
#define PJ_SMEM (55296 + 10240)

__global__ __launch_bounds__(256, 2)
void proj_wmma_kernel(const float* __restrict__ xq, const float* __restrict__ xk,
                      const float* __restrict__ xv,
                      const float* __restrict__ Wq, const float* __restrict__ Wk,
                      const float* __restrict__ Wv)
{
    extern __shared__ char sm[];
    __nv_bfloat16* Whi = (__nv_bfloat16*)(sm + PJ_WHI);
    __nv_bfloat16* Wlo = (__nv_bfloat16*)(sm + PJ_WLO);
    __nv_bfloat16* Xhi = (__nv_bfloat16*)(sm + PJ_XHI);
    __nv_bfloat16* Xlo = (__nv_bfloat16*)(sm + PJ_XLO);

    const int which = blockIdx.z;
    const float* X; const float* W; __nv_bfloat16* Yh; __nv_bfloat16* Yl;
    if (which == 0)      { X = xq; W = Wq; Yh = g_qh; Yl = g_ql; }
    else if (which == 1) { X = xk; W = Wk; Yh = g_kh; Yl = g_kl; }
    else                 { X = xv; W = Wv; Yh = g_vh; Yl = g_vl; }

    const int nh = blockIdx.y;
    const int n  = nh / HEADS;
    const int h  = nh % HEADS;
    const int s0 = blockIdx.x * 128;
    const int tid = threadIdx.x, wid = tid >> 5, lane = tid & 31;
    float* scr = (float*)(sm + PJ_SCR) + wid * (16 * PSCR);

    stage_rows_f32(X + (size_t)(n * S_LEN + s0) * EMB + h * HD, EMB,
                   (char*)Xhi, (char*)Xlo, tid);
    if (tid < 128)
        stage_rows_f32(W, HD, (char*)Whi, (char*)Wlo, tid);
    __syncthreads();

    wmma::fragment<wmma::accumulator, 16, 16, 16, float> acc[4];
#pragma unroll
    for (int j = 0; j < 4; j++) wmma::fill_fragment(acc[j], 0.0f);

#pragma unroll
    for (int kk = 0; kk < 4; kk++) {
        wmma::fragment<wmma::matrix_a, 16, 16, 16, __nv_bfloat16, wmma::row_major> ah, al;
        wmma::load_matrix_sync(ah, Xhi + wid * 16 * PT + kk * 16, PT);
        wmma::load_matrix_sync(al, Xlo + wid * 16 * PT + kk * 16, PT);
#pragma unroll
        for (int j = 0; j < 4; j++) {
            wmma::fragment<wmma::matrix_b, 16, 16, 16, __nv_bfloat16, wmma::col_major> bh, bl;
            wmma::load_matrix_sync(bh, Whi + j * 16 * PT + kk * 16, PT);
            wmma::load_matrix_sync(bl, Wlo + j * 16 * PT + kk * 16, PT);
            wmma::mma_sync(acc[j], ah, bh, acc[j]);
            wmma::mma_sync(acc[j], ah, bl, acc[j]);
            wmma::mma_sync(acc[j], al, bh, acc[j]);
        }
    }

    // epilogue: split result to hi/lo bf16 and store
    const int r = lane >> 1, cw = lane & 1;
    const size_t ybase = (size_t)((n * HEADS + h) * S_LEN + s0 + wid * 16) * HD;
#pragma unroll
    for (int j = 0; j < 4; j++) {
        wmma::store_matrix_sync(scr, acc[j], PSCR, wmma::mem_row_major);
        __syncwarp();
        const float* s = scr + r * PSCR + cw * 8;
        uint32_t H[4], L[4];
#pragma unroll
        for (int u = 0; u < 4; u++) split2(s[2 * u], s[2 * u + 1], H[u], L[u]);
        const size_t off = ybase + (size_t)r * HD + j * 16 + cw * 8;
        *(uint4*)(Yh + off) = make_uint4(H[0], H[1], H[2], H[3]);
        *(uint4*)(Yl + off) = make_uint4(L[0], L[1], L[2], L[3]);
        __syncwarp();
    }
}

// ---------------------------------------------------------------------------
// Kernel 2: mma.sync flash attention — pre-split inputs, register softmax
// grid (HEADS, S_LEN/128, N_B), 256 threads, kv-tile 32
// ---------------------------------------------------------------------------
#define A_QHI  0
#define A_QLO  18432
#define A_KHI  36864
#define A_KLO  41472
#define A_VHI  46080
#define A_VLO  50688
#define ATTN_SMEM (55296 + 256)

__global__ __launch_bounds__(256, 2)
void attn_mma_kernel()
{
    extern __shared__ char sm[];
    const int tid = threadIdx.x, wid = tid >> 5, lane = tid & 31;
    const int h = blockIdx.x, qt = blockIdx.y, n = blockIdx.z;
    const int q0 = qt * 128;

    const size_t head_base = (size_t)(n * HEADS + h) * S_LEN * HD;
    const __nv_bfloat16* Qh = g_qh + head_base + (size_t)q0 * HD;
    const __nv_bfloat16* Ql = g_ql + head_base + (size_t)q0 * HD;
    const __nv_bfloat16* Kh = g_kh + head_base;
    const __nv_bfloat16* Kl = g_kl + head_base;
    const __nv_bfloat16* Vh = g_vh + head_base;
    const __nv_bfloat16* Vl = g_vl + head_base;

    // ---- stage Q (bf16 copy): t -> row=t>>1, half 32 cols ----
    {
        const int r = tid >> 1, half = tid & 1;
        const char* sh0 = (const char*)(Qh + (size_t)r * HD + half * 32);
        const char* sl0 = (const char*)(Ql + (size_t)r * HD + half * 32);
        uint32_t off = (uint32_t)(r * (PT * 2) + half * 64);
#pragma unroll
        for (int tt = 0; tt < 4; tt++) {
            *(uint4*)(sm + A_QHI + off + tt * 16) = *(const uint4*)(sh0 + tt * 16);
            *(uint4*)(sm + A_QLO + off + tt * 16) = *(const uint4*)(sl0 + tt * 16);
        }
    }
    __syncthreads();

    const int l7  = lane & 7;
    const int s01 = (lane >> 3) & 1;
    const int s23 = (lane >> 4) & 1;

    uint32_t qh[4][4], ql[4][4];
    {
        uint32_t base = smem_u32(sm) +
                        (uint32_t)((wid * 16 + l7 + s01 * 8) * (PT * 2)) + s23 * 16;
#pragma unroll
        for (int c = 0; c < 4; c++) {
            ldsm_x4(qh[c], base + A_QHI + c * 32);
            ldsm_x4(ql[c], base + A_QLO + c * 32);
        }
    }

    const int g   = lane >> 2;
    const int tig = lane & 3;
    const int qrow_g  = q0 + wid * 16 + g;
    const unsigned* mrow0 = g_mbits + (size_t)(n * S_LEN + qrow_g) * MWORDS;
    const unsigned* mrow8 = mrow0 + 8 * MWORDS;

    const uint32_t smb = smem_u32(sm);
    const uint32_t kbase = smb + (uint32_t)(l7 * (PT * 2)) + s01 * 16;
    const uint32_t vbase = smb + (uint32_t)((l7 + 8 * s01) * (PT * 2));

    float o[8][4];
#pragma unroll
    for (int j = 0; j < 8; j++)
#pragma unroll
        for (int u = 0; u < 4; u++) o[j][u] = 0.f;
    float lsum_g = 0.f, lsum_8 = 0.f;

    const float SC = 0.03125f;
    const int str = tid >> 3, soct = tid & 7;        // staging: row, 8-col oct

    for (int it = 0; it < S_LEN / 32; it++) {
        __syncthreads();
        {
            const size_t gsrc = (size_t)(it * 32 + str) * HD + soct * 8;
            const uint32_t soff = (uint32_t)(str * (PT * 2) + soct * 16);
            *(uint4*)(sm + A_KHI + soff) = *(const uint4*)(Kh + gsrc);
            *(uint4*)(sm + A_KLO + soff) = *(const uint4*)(Kl + gsrc);
            *(uint4*)(sm + A_VHI + soff) = *(const uint4*)(Vh + gsrc);
            *(uint4*)(sm + A_VLO + soff) = *(const uint4*)(Vl + gsrc);
        }
        __syncthreads();

        // ---- S = Q K^T ----
        float s[4][4];
#pragma unroll
        for (int j = 0; j < 4; j++)
#pragma unroll
            for (int u = 0; u < 4; u++) s[j][u] = 0.f;

#pragma unroll
        for (int c = 0; c < 4; c++) {
#pragma unroll
            for (int j = 0; j < 4; j++) {
                uint32_t bh[2], bl[2];
                uint32_t ka = kbase + (uint32_t)(j * 8 * (PT * 2)) + c * 32;
                ldsm_x2(bh, ka + A_KHI);
                ldsm_x2(bl, ka + A_KLO);
                mma16816(s[j], qh[c], bh);
                mma16816(s[j], qh[c], bl);
                mma16816(s[j], ql[c], bh);
            }
        }

        // ---- softmax in registers ----
        const unsigned w0 = mrow0[it];
        const unsigned w8 = mrow8[it];
#pragma unroll
        for (int j = 0; j < 4; j++) {
            const int bit = j * 8 + tig * 2;
            float p0 = __expf(s[j][0] * SC);
            float p1 = __expf(s[j][1] * SC);
            float p2 = __expf(s[j][2] * SC);
            float p3 = __expf(s[j][3] * SC);
            p0 = ((w0 >> bit) & 1u)       ? p0 : 0.f;
            p1 = ((w0 >> (bit + 1)) & 1u) ? p1 : 0.f;
            p2 = ((w8 >> bit) & 1u)       ? p2 : 0.f;
            p3 = ((w8 >> (bit + 1)) & 1u) ? p3 : 0.f;
            lsum_g += p0 + p1;
            lsum_8 += p2 + p3;
            s[j][0] = p0; s[j][1] = p1; s[j][2] = p2; s[j][3] = p3;
        }

        // ---- O += P V ----
#pragma unroll
        for (int c2 = 0; c2 < 2; c2++) {
            uint32_t ah[4], al[4];
            split2(s[2 * c2][0],     s[2 * c2][1],     ah[0], al[0]);
            split2(s[2 * c2][2],     s[2 * c2][3],     ah[1], al[1]);
            split2(s[2 * c2 + 1][0], s[2 * c2 + 1][1], ah[2], al[2]);
            split2(s[2 * c2 + 1][2], s[2 * c2 + 1][3], ah[3], al[3]);
#pragma unroll
            for (int j = 0; j < 8; j++) {
                uint32_t bh[2], bl[2];
                uint32_t va = vbase + (uint32_t)(c2 * 16 * (PT * 2)) + j * 16;
                ldsm_x2_t(bh, va + A_VHI);
                ldsm_x2_t(bl, va + A_VLO);
                mma16816(o[j], ah, bh);
                mma16816(o[j], ah, bl);
                mma16816(o[j], al, bh);
            }
        }
    }

    // ---- epilogue: normalize, split to hi/lo, store ----
    lsum_g += __shfl_xor_sync(0xffffffffu, lsum_g, 1);
    lsum_g += __shfl_xor_sync(0xffffffffu, lsum_g, 2);
    lsum_8 += __shfl_xor_sync(0xffffffffu, lsum_8, 1);
    lsum_8 += __shfl_xor_sync(0xffffffffu, lsum_8, 2);
    const float inv_g = 1.0f / lsum_g;
    const float inv_8 = 1.0f / lsum_8;

    const size_t d0 = (size_t)(n * S_LEN + qrow_g) * EMB + h * HD;
    const size_t d8 = d0 + (size_t)8 * EMB;
#pragma unroll
    for (int j = 0; j < 8; j++) {
        const int col = j * 8 + tig * 2;
        uint32_t H, L;
        split2(o[j][0] * inv_g, o[j][1] * inv_g, H, L);
        *(uint32_t*)(g_aoh + d0 + col) = H;
        *(uint32_t*)(g_aol + d0 + col) = L;
        split2(o[j][2] * inv_8, o[j][3] * inv_8, H, L);
        *(uint32_t*)(g_aoh + d8 + col) = H;
        *(uint32_t*)(g_aol + d8 + col) = L;
    }
}

// ---------------------------------------------------------------------------
// Kernel 3: output projection — pre-split A and B, BK=16
// ---------------------------------------------------------------------------
#define PK 24

__global__ __launch_bounds__(256)
void out_wmma_kernel(const float* __restrict__ bo, float* __restrict__ out)
{
    __shared__ __nv_bfloat16 Ahi[128 * PK], Alo[128 * PK];
    __shared__ __nv_bfloat16 Bhi[128 * PK], Blo[128 * PK];
    __shared__ float scrs[8 * 16 * PSCR];

    const int tid = threadIdx.x, wid = tid >> 5, lane = tid & 31;
    const int r0 = blockIdx.y * 128;
    const int e0 = blockIdx.x * 128;
    const int wr = wid & 3;
    const int wc = wid >> 2;
    float* scr = scrs + wid * (16 * PSCR);

    wmma::fragment<wmma::accumulator, 16, 16, 16, float> acc[2][4];
#pragma unroll
    for (int i = 0; i < 2; i++)
#pragma unroll
        for (int j = 0; j < 4; j++) wmma::fill_fragment(acc[i][j], 0.0f);

    const int sr = tid >> 1;
    const int sh = tid & 1;

    for (int c0 = 0; c0 < EMB; c0 += 16) {
        __syncthreads();
        {
            const size_t asrc = (size_t)(r0 + sr) * EMB + c0 + sh * 8;
            const size_t bsrc = (size_t)(e0 + sr) * EMB + c0 + sh * 8;
            const uint32_t off = (uint32_t)(sr * (PK * 2) + sh * 16);
            *(uint4*)((char*)Ahi + off) = *(const uint4*)(g_aoh + asrc);
            *(uint4*)((char*)Alo + off) = *(const uint4*)(g_aol + asrc);
            *(uint4*)((char*)Bhi + off) = *(const uint4*)(g_woh + bsrc);
            *(uint4*)((char*)Blo + off) = *(const uint4*)(g_wol + bsrc);
        }
        __syncthreads();

        wmma::fragment<wmma::matrix_a, 16, 16, 16, __nv_bfloat16, wmma::row_major> ah[2], al[2];
#pragma unroll
        for (int i = 0; i < 2; i++) {
            wmma::load_matrix_sync(ah[i], Ahi + (wr * 32 + i * 16) * PK, PK);
            wmma::load_matrix_sync(al[i], Alo + (wr * 32 + i * 16) * PK, PK);
        }
#pragma unroll
        for (int j = 0; j < 4; j++) {
            wmma::fragment<wmma::matrix_b, 16, 16, 16, __nv_bfloat16, wmma::col_major> bh, bl;
            wmma::load_matrix_sync(bh, Bhi + (wc * 64 + j * 16) * PK, PK);
            wmma::load_matrix_sync(bl, Blo + (wc * 64 + j * 16) * PK, PK);
#pragma unroll
            for (int i = 0; i < 2; i++) {
                wmma::mma_sync(acc[i][j], ah[i], bh, acc[i][j]);
                wmma::mma_sync(acc[i][j], ah[i], bl, acc[i][j]);
                wmma::mma_sync(acc[i][j], al[i], bh, acc[i][j]);
            }
        }
    }

    const int r = lane >> 1, cw = lane & 1;
#pragma unroll
    for (int i = 0; i < 2; i++)
#pragma unroll
        for (int j = 0; j < 4; j++) {
            wmma::store_matrix_sync(scr, acc[i][j], PSCR, wmma::mem_row_major);
            __syncwarp();
            const int row = r0 + wr * 32 + i * 16 + r;
            const int col = e0 + wc * 64 + j * 16 + cw * 8;
            const float4 bv0 = *(const float4*)(bo + col);
            const float4 bv1 = *(const float4*)(bo + col + 4);
            const float* s = scr + r * PSCR + cw * 8;
            float4 o0 = make_float4(s[0] + bv0.x, s[1] + bv0.y, s[2] + bv0.z, s[3] + bv0.w);
            float4 o1 = make_float4(s[4] + bv1.x, s[5] + bv1.y, s[6] + bv1.z, s[7] + bv1.w);
            *(float4*)(out + (size_t)row * EMB + col)     = o0;
            *(float4*)(out + (size_t)row * EMB + col + 4) = o1;
            __syncwarp();
        }
}

// ---------------------------------------------------------------------------
extern "C" void kernel_launch(void* const* d_in, const int* in_sizes, int n_in,
                              void* d_out, int out_size)
{
    const float* values  = (const float*)d_in[0];
    const float* queries = (const float*)d_in[1];
    const float* keys    = (const float*)d_in[2];
    const int*   mask    = (const int*)  d_in[3];
    const float* Wv      = (const float*)d_in[4];
    const float* Wk      = (const float*)d_in[5];
    const float* Wq      = (const float*)d_in[6];
    const float* Wo      = (const float*)d_in[7];
    const float* bo      = (const float*)d_in[8];
    float* out = (float*)d_out;

    static bool attr_set = false;
    if (!attr_set) {
        cudaFuncSetAttribute(proj_wmma_kernel,
                             cudaFuncAttributeMaxDynamicSharedMemorySize, PJ_SMEM);
        cudaFuncSetAttribute(attn_mma_kernel,
                             cudaFuncAttributeMaxDynamicSharedMemorySize, ATTN_SMEM);
        attr_set = true;
    }

    mask_pack_kernel<<<(N_B * S_LEN * MWORDS * 32) / 256, 256>>>(mask);
    wo_split_kernel<<<(EMB * EMB) / (256 * 8), 256>>>(Wo);

    dim3 pgrid(S_LEN / 128, N_B * HEADS, 3);
    proj_wmma_kernel<<<pgrid, 256, PJ_SMEM>>>(queries, keys, values, Wq, Wk, Wv);

    dim3 agrid(HEADS, S_LEN / 128, N_B);
    attn_mma_kernel<<<agrid, 256, ATTN_SMEM>>>();

    dim3 ggrid(EMB / 128, (N_B * S_LEN) / 128);
    out_wmma_kernel<<<ggrid, 256>>>(bo, out);
}

// round 8
// speedup vs baseline: 3.5709x; 1.1238x over previous
#include <cuda_runtime.h>
#include <cuda_bf16.h>
#include <mma.h>
#include <cstdint>

using namespace nvcuda;

#define N_B    4
#define S_LEN  2048
#define EMB    1024
#define HEADS  16
#define HD     64
#define MWORDS (S_LEN / 32)

#define PT   72    // bf16 smem pitch (144 B rows)
#define PSCR 20

// ---------------- scratch (device globals) ---------------------------------
__device__ __nv_bfloat16 g_qh[N_B * HEADS * S_LEN * HD];
__device__ __nv_bfloat16 g_ql[N_B * HEADS * S_LEN * HD];
__device__ __nv_bfloat16 g_kh[N_B * HEADS * S_LEN * HD];
__device__ __nv_bfloat16 g_kl[N_B * HEADS * S_LEN * HD];
__device__ __nv_bfloat16 g_vh[N_B * HEADS * S_LEN * HD];
__device__ __nv_bfloat16 g_vl[N_B * HEADS * S_LEN * HD];
__device__ __nv_bfloat16 g_aoh[N_B * S_LEN * EMB];
__device__ __nv_bfloat16 g_aol[N_B * S_LEN * EMB];
__device__ __nv_bfloat16 g_woh[EMB * EMB];
__device__ __nv_bfloat16 g_wol[EMB * EMB];
__device__ unsigned g_mbits[N_B * S_LEN * MWORDS];

__device__ __forceinline__ void split2(float x0, float x1, uint32_t& hi, uint32_t& lo) {
    __nv_bfloat16 h0 = __float2bfloat16_rn(x0), h1 = __float2bfloat16_rn(x1);
    float r0 = x0 - __bfloat162float(h0), r1 = x1 - __bfloat162float(h1);
    __nv_bfloat16 l0 = __float2bfloat16_rn(r0), l1 = __float2bfloat16_rn(r1);
    __nv_bfloat162 hp; hp.x = h0; hp.y = h1;
    __nv_bfloat162 lp; lp.x = l0; lp.y = l1;
    hi = *reinterpret_cast<uint32_t*>(&hp);
    lo = *reinterpret_cast<uint32_t*>(&lp);
}

__device__ __forceinline__ uint32_t smem_u32(const void* p) {
    uint32_t a;
    asm("{ .reg .u64 t; cvta.to.shared.u64 t, %1; cvt.u32.u64 %0, t; }"
        : "=r"(a) : "l"(p));
    return a;
}

// ---- tensor-core / async-copy primitives ----------------------------------
__device__ __forceinline__ void ldsm_x4(uint32_t* r, uint32_t addr) {
    asm volatile("ldmatrix.sync.aligned.m8n8.x4.shared.b16 {%0,%1,%2,%3}, [%4];"
                 : "=r"(r[0]), "=r"(r[1]), "=r"(r[2]), "=r"(r[3]) : "r"(addr));
}
__device__ __forceinline__ void ldsm_x4_t(uint32_t* r, uint32_t addr) {
    asm volatile("ldmatrix.sync.aligned.m8n8.x4.trans.shared.b16 {%0,%1,%2,%3}, [%4];"
                 : "=r"(r[0]), "=r"(r[1]), "=r"(r[2]), "=r"(r[3]) : "r"(addr));
}
__device__ __forceinline__ void mma16816(float* d, const uint32_t* a, const uint32_t* b) {
    asm volatile(
        "mma.sync.aligned.m16n8k16.row.col.f32.bf16.bf16.f32 "
        "{%0,%1,%2,%3}, {%4,%5,%6,%7}, {%8,%9}, {%0,%1,%2,%3};"
        : "+f"(d[0]), "+f"(d[1]), "+f"(d[2]), "+f"(d[3])
        : "r"(a[0]), "r"(a[1]), "r"(a[2]), "r"(a[3]), "r"(b[0]), "r"(b[1]));
}
__device__ __forceinline__ void cp16(uint32_t dst, const void* src) {
    asm volatile("cp.async.cg.shared.global [%0], [%1], 16;" :: "r"(dst), "l"(src));
}
#define CP_COMMIT() asm volatile("cp.async.commit_group;" ::: "memory")
#define CP_WAIT0()  asm volatile("cp.async.wait_group 0;" ::: "memory")

// stage nrows x 64 f32 -> bf16 hi/lo smem pitch PT (proj only)
__device__ __forceinline__ void stage_rows_f32(const float* __restrict__ src, size_t stride,
                                               char* s_hi, char* s_lo, int t)
{
    const int r    = t >> 1;
    const int half = t & 1;
    const float4* s4 = (const float4*)(src + (size_t)r * stride) + half * 8;
#pragma unroll
    for (int tt = 0; tt < 4; tt++) {
        float4 a = s4[2 * tt], b = s4[2 * tt + 1];
        float f[8] = {a.x, a.y, a.z, a.w, b.x, b.y, b.z, b.w};
        uint32_t H[4], L[4];
#pragma unroll
        for (int u = 0; u < 4; u++) split2(f[2 * u], f[2 * u + 1], H[u], L[u]);
        uint32_t off = (uint32_t)(r * (PT * 2) + half * 64 + tt * 16);
        *(uint4*)(s_hi + off) = make_uint4(H[0], H[1], H[2], H[3]);
        *(uint4*)(s_lo + off) = make_uint4(L[0], L[1], L[2], L[3]);
    }
}

// ---------------------------------------------------------------------------
// Kernel 0a: pack mask bits
// ---------------------------------------------------------------------------
__global__ __launch_bounds__(256)
void mask_pack_kernel(const int* __restrict__ mask)
{
    int gid  = blockIdx.x * 256 + threadIdx.x;
    int w    = gid >> 5;
    int lane = gid & 31;
    int v = mask[(size_t)w * 32 + lane];
    unsigned bits = __ballot_sync(0xffffffffu, v != 0);
    if (lane == 0) g_mbits[w] = bits;
}

// ---------------------------------------------------------------------------
// Kernel 0b: pre-split Wo (once)
// ---------------------------------------------------------------------------
__global__ __launch_bounds__(256)
void wo_split_kernel(const float* __restrict__ Wo)
{
    size_t idx = ((size_t)blockIdx.x * 256 + threadIdx.x) * 8;
    float4 a = *(const float4*)(Wo + idx);
    float4 b = *(const float4*)(Wo + idx + 4);
    float f[8] = {a.x, a.y, a.z, a.w, b.x, b.y, b.z, b.w};
    uint32_t H[4], L[4];
#pragma unroll
    for (int u = 0; u < 4; u++) split2(f[2 * u], f[2 * u + 1], H[u], L[u]);
    *(uint4*)(g_woh + idx) = make_uint4(H[0], H[1], H[2], H[3]);
    *(uint4*)(g_wol + idx) = make_uint4(L[0], L[1], L[2], L[3]);
}

// ---------------------------------------------------------------------------
// Kernel 1: projections (unchanged from R7)
// ---------------------------------------------------------------------------
#define PJ_WHI 0
#define PJ_WLO 9216
#define PJ_XHI 18432
#define PJ_XLO 36864
#define PJ_SCR 55296
#define PJ_SMEM (55296 + 10240)

__global__ __launch_bounds__(256, 2)
void proj_wmma_kernel(const float* __restrict__ xq, const float* __restrict__ xk,
                      const float* __restrict__ xv,
                      const float* __restrict__ Wq, const float* __restrict__ Wk,
                      const float* __restrict__ Wv)
{
    extern __shared__ char sm[];
    __nv_bfloat16* Whi = (__nv_bfloat16*)(sm + PJ_WHI);
    __nv_bfloat16* Wlo = (__nv_bfloat16*)(sm + PJ_WLO);
    __nv_bfloat16* Xhi = (__nv_bfloat16*)(sm + PJ_XHI);
    __nv_bfloat16* Xlo = (__nv_bfloat16*)(sm + PJ_XLO);

    const int which = blockIdx.z;
    const float* X; const float* W; __nv_bfloat16* Yh; __nv_bfloat16* Yl;
    if (which == 0)      { X = xq; W = Wq; Yh = g_qh; Yl = g_ql; }
    else if (which == 1) { X = xk; W = Wk; Yh = g_kh; Yl = g_kl; }
    else                 { X = xv; W = Wv; Yh = g_vh; Yl = g_vl; }

    const int nh = blockIdx.y;
    const int n  = nh / HEADS;
    const int h  = nh % HEADS;
    const int s0 = blockIdx.x * 128;
    const int tid = threadIdx.x, wid = tid >> 5, lane = tid & 31;
    float* scr = (float*)(sm + PJ_SCR) + wid * (16 * PSCR);

    stage_rows_f32(X + (size_t)(n * S_LEN + s0) * EMB + h * HD, EMB,
                   (char*)Xhi, (char*)Xlo, tid);
    if (tid < 128)
        stage_rows_f32(W, HD, (char*)Whi, (char*)Wlo, tid);
    __syncthreads();

    wmma::fragment<wmma::accumulator, 16, 16, 16, float> acc[4];
#pragma unroll
    for (int j = 0; j < 4; j++) wmma::fill_fragment(acc[j], 0.0f);

#pragma unroll
    for (int kk = 0; kk < 4; kk++) {
        wmma::fragment<wmma::matrix_a, 16, 16, 16, __nv_bfloat16, wmma::row_major> ah, al;
        wmma::load_matrix_sync(ah, Xhi + wid * 16 * PT + kk * 16, PT);
        wmma::load_matrix_sync(al, Xlo + wid * 16 * PT + kk * 16, PT);
#pragma unroll
        for (int j = 0; j < 4; j++) {
            wmma::fragment<wmma::matrix_b, 16, 16, 16, __nv_bfloat16, wmma::col_major> bh, bl;
            wmma::load_matrix_sync(bh, Whi + j * 16 * PT + kk * 16, PT);
            wmma::load_matrix_sync(bl, Wlo + j * 16 * PT + kk * 16, PT);
            wmma::mma_sync(acc[j], ah, bh, acc[j]);
            wmma::mma_sync(acc[j], ah, bl, acc[j]);
            wmma::mma_sync(acc[j], al, bh, acc[j]);
        }
    }

    const int r = lane >> 1, cw = lane & 1;
    const size_t ybase = (size_t)((n * HEADS + h) * S_LEN + s0 + wid * 16) * HD;
#pragma unroll
    for (int j = 0; j < 4; j++) {
        wmma::store_matrix_sync(scr, acc[j], PSCR, wmma::mem_row_major);
        __syncwarp();
        const float* s = scr + r * PSCR + cw * 8;
        uint32_t H[4], L[4];
#pragma unroll
        for (int u = 0; u < 4; u++) split2(s[2 * u], s[2 * u + 1], H[u], L[u]);
        const size_t off = ybase + (size_t)r * HD + j * 16 + cw * 8;
        *(uint4*)(Yh + off) = make_uint4(H[0], H[1], H[2], H[3]);
        *(uint4*)(Yl + off) = make_uint4(L[0], L[1], L[2], L[3]);
        __syncwarp();
    }
}

// ---------------------------------------------------------------------------
// Kernel 2: flash attention — x4 ldmatrix, cp.async double-buffered K/V
// grid (HEADS, S_LEN/128, N_B), 256 threads, kv-tile 32
// smem: Q 36864 + 2 KV buffers of 18432 (KHI 0 / KLO 4608 / VHI 9216 / VLO 13824)
// ---------------------------------------------------------------------------
#define A_QHI  0
#define A_QLO  18432
#define A_KV0  36864
#define A_KV1  55296
#define KV_KLO 4608
#define KV_VHI 9216
#define KV_VLO 13824
#define ATTN_SMEM (73728 + 256)
#define NIT (S_LEN / 32)

__global__ __launch_bounds__(256, 2)
void attn_mma_kernel()
{
    extern __shared__ char sm[];
    const int tid = threadIdx.x, wid = tid >> 5, lane = tid & 31;
    const int h = blockIdx.x, qt = blockIdx.y, n = blockIdx.z;
    const int q0 = qt * 128;

    const size_t head_base = (size_t)(n * HEADS + h) * S_LEN * HD;
    const __nv_bfloat16* Qh = g_qh + head_base + (size_t)q0 * HD;
    const __nv_bfloat16* Ql = g_ql + head_base + (size_t)q0 * HD;
    const __nv_bfloat16* Kh = g_kh + head_base;
    const __nv_bfloat16* Kl = g_kl + head_base;
    const __nv_bfloat16* Vh = g_vh + head_base;
    const __nv_bfloat16* Vl = g_vl + head_base;

    const uint32_t smb = smem_u32(sm);

    // ---- async prefetch of KV tile 0 into buffer 0 ----
    const int str = tid >> 3, soct = tid & 7;
    const uint32_t soff = (uint32_t)(str * (PT * 2) + soct * 16);
    {
        const size_t gsrc = (size_t)str * HD + soct * 8;
        const uint32_t d = smb + A_KV0 + soff;
        cp16(d,           Kh + gsrc);
        cp16(d + KV_KLO,  Kl + gsrc);
        cp16(d + KV_VHI,  Vh + gsrc);
        cp16(d + KV_VLO,  Vl + gsrc);
    }
    CP_COMMIT();

    // ---- stage Q (plain copy), hoist fragments ----
    {
        const int r = tid >> 1, half = tid & 1;
        const char* sh0 = (const char*)(Qh + (size_t)r * HD + half * 32);
        const char* sl0 = (const char*)(Ql + (size_t)r * HD + half * 32);
        uint32_t off = (uint32_t)(r * (PT * 2) + half * 64);
#pragma unroll
        for (int tt = 0; tt < 4; tt++) {
            *(uint4*)(sm + A_QHI + off + tt * 16) = *(const uint4*)(sh0 + tt * 16);
            *(uint4*)(sm + A_QLO + off + tt * 16) = *(const uint4*)(sl0 + tt * 16);
        }
    }
    __syncthreads();

    const int l7  = lane & 7;
    const int s01 = (lane >> 3) & 1;
    const int s23 = (lane >> 4) & 1;

    uint32_t qh[4][4], ql[4][4];
    {
        uint32_t base = smb + (uint32_t)((wid * 16 + l7 + s01 * 8) * (PT * 2)) + s23 * 16;
#pragma unroll
        for (int c = 0; c < 4; c++) {
            ldsm_x4(qh[c], base + A_QHI + c * 32);
            ldsm_x4(ql[c], base + A_QLO + c * 32);
        }
    }

    const int g   = lane >> 2;
    const int tig = lane & 3;
    const int qrow_g  = q0 + wid * 16 + g;
    const unsigned* mrow0 = g_mbits + (size_t)(n * S_LEN + qrow_g) * MWORDS;
    const unsigned* mrow8 = mrow0 + 8 * MWORDS;

    // x4 lane-dependent offsets
    const uint32_t kqoff = (uint32_t)(((lane >> 4) * 8 + l7) * (PT * 2)) + ((lane >> 3) & 1) * 16;
    const uint32_t voff  = (uint32_t)((((lane >> 3) & 1) * 8 + l7) * (PT * 2)) + (lane >> 4) * 16;

    float o[8][4];
#pragma unroll
    for (int j = 0; j < 8; j++)
#pragma unroll
        for (int u = 0; u < 4; u++) o[j][u] = 0.f;
    float lsum_g = 0.f, lsum_8 = 0.f;

    const float SC = 0.03125f;

    for (int it = 0; it < NIT; it++) {
        const uint32_t kv = smb + ((it & 1) ? A_KV1 : A_KV0);

        CP_WAIT0();
        __syncthreads();

        // prefetch next tile into the other buffer
        if (it + 1 < NIT) {
            const size_t gsrc = (size_t)((it + 1) * 32 + str) * HD + soct * 8;
            const uint32_t d = smb + (((it + 1) & 1) ? A_KV1 : A_KV0) + soff;
            cp16(d,           Kh + gsrc);
            cp16(d + KV_KLO,  Kl + gsrc);
            cp16(d + KV_VHI,  Vh + gsrc);
            cp16(d + KV_VLO,  Vl + gsrc);
        }
        CP_COMMIT();

        // ---- S = Q K^T (x4: two n-tiles per ldmatrix) ----
        float s[4][4];
#pragma unroll
        for (int j = 0; j < 4; j++)
#pragma unroll
            for (int u = 0; u < 4; u++) s[j][u] = 0.f;

#pragma unroll
        for (int c = 0; c < 4; c++) {
#pragma unroll
            for (int jp = 0; jp < 2; jp++) {
                uint32_t bh[4], bl[4];
                uint32_t ka = kv + kqoff + (uint32_t)(jp * 16 * (PT * 2)) + c * 32;
                ldsm_x4(bh, ka);
                ldsm_x4(bl, ka + KV_KLO);
                mma16816(s[2 * jp],     qh[c], bh);
                mma16816(s[2 * jp],     qh[c], bl);
                mma16816(s[2 * jp],     ql[c], bh);
                mma16816(s[2 * jp + 1], qh[c], bh + 2);
                mma16816(s[2 * jp + 1], qh[c], bl + 2);
                mma16816(s[2 * jp + 1], ql[c], bh + 2);
            }
        }

        // ---- softmax in registers ----
        const unsigned w0 = mrow0[it];
        const unsigned w8 = mrow8[it];
#pragma unroll
        for (int j = 0; j < 4; j++) {
            const int bit = j * 8 + tig * 2;
            float p0 = __expf(s[j][0] * SC);
            float p1 = __expf(s[j][1] * SC);
            float p2 = __expf(s[j][2] * SC);
            float p3 = __expf(s[j][3] * SC);
            p0 = ((w0 >> bit) & 1u)       ? p0 : 0.f;
            p1 = ((w0 >> (bit + 1)) & 1u) ? p1 : 0.f;
            p2 = ((w8 >> bit) & 1u)       ? p2 : 0.f;
            p3 = ((w8 >> (bit + 1)) & 1u) ? p3 : 0.f;
            lsum_g += p0 + p1;
            lsum_8 += p2 + p3;
            s[j][0] = p0; s[j][1] = p1; s[j][2] = p2; s[j][3] = p3;
        }

        // ---- O += P V (x4.trans: two d-tiles per ldmatrix) ----
#pragma unroll
        for (int c2 = 0; c2 < 2; c2++) {
            uint32_t ah[4], al[4];
            split2(s[2 * c2][0],     s[2 * c2][1],     ah[0], al[0]);
            split2(s[2 * c2][2],     s[2 * c2][3],     ah[1], al[1]);
            split2(s[2 * c2 + 1][0], s[2 * c2 + 1][1], ah[2], al[2]);
            split2(s[2 * c2 + 1][2], s[2 * c2 + 1][3], ah[3], al[3]);
#pragma unroll
            for (int jp = 0; jp < 4; jp++) {
                uint32_t bh[4], bl[4];
                uint32_t va = kv + KV_VHI + voff + (uint32_t)(c2 * 16 * (PT * 2)) + jp * 32;
                ldsm_x4_t(bh, va);
                ldsm_x4_t(bl, va + (KV_VLO - KV_VHI));
                mma16816(o[2 * jp],     ah, bh);
                mma16816(o[2 * jp],     ah, bl);
                mma16816(o[2 * jp],     al, bh);
                mma16816(o[2 * jp + 1], ah, bh + 2);
                mma16816(o[2 * jp + 1], ah, bl + 2);
                mma16816(o[2 * jp + 1], al, bh + 2);
            }
        }
    }

    // ---- epilogue ----
    lsum_g += __shfl_xor_sync(0xffffffffu, lsum_g, 1);
    lsum_g += __shfl_xor_sync(0xffffffffu, lsum_g, 2);
    lsum_8 += __shfl_xor_sync(0xffffffffu, lsum_8, 1);
    lsum_8 += __shfl_xor_sync(0xffffffffu, lsum_8, 2);
    const float inv_g = 1.0f / lsum_g;
    const float inv_8 = 1.0f / lsum_8;

    const size_t d0 = (size_t)(n * S_LEN + qrow_g) * EMB + h * HD;
    const size_t d8 = d0 + (size_t)8 * EMB;
#pragma unroll
    for (int j = 0; j < 8; j++) {
        const int col = j * 8 + tig * 2;
        uint32_t H, L;
        split2(o[j][0] * inv_g, o[j][1] * inv_g, H, L);
        *(uint32_t*)(g_aoh + d0 + col) = H;
        *(uint32_t*)(g_aol + d0 + col) = L;
        split2(o[j][2] * inv_8, o[j][3] * inv_8, H, L);
        *(uint32_t*)(g_aoh + d8 + col) = H;
        *(uint32_t*)(g_aol + d8 + col) = L;
    }
}

// ---------------------------------------------------------------------------
// Kernel 3: output projection — cp.async double-buffered, BK=16
// per buffer: Ahi 0 / Alo 6144 / Bhi 12288 / Blo 18432 (24576 B); 2 buffers
// ---------------------------------------------------------------------------
#define PK 24
#define OB_SZ   24576
#define OB_ALO  6144
#define OB_BHI  12288
#define OB_BLO  18432
#define O_SCR   49152
#define OUT_SMEM (49152 + 10240)

__global__ __launch_bounds__(256, 2)
void out_wmma_kernel(const float* __restrict__ bo, float* __restrict__ out)
{
    extern __shared__ char sm[];
    const uint32_t smb = smem_u32(sm);

    const int tid = threadIdx.x, wid = tid >> 5, lane = tid & 31;
    const int r0 = blockIdx.y * 128;
    const int e0 = blockIdx.x * 128;
    const int wr = wid & 3;
    const int wc = wid >> 2;
    float* scr = (float*)(sm + O_SCR) + wid * (16 * PSCR);

    wmma::fragment<wmma::accumulator, 16, 16, 16, float> acc[2][4];
#pragma unroll
    for (int i = 0; i < 2; i++)
#pragma unroll
        for (int j = 0; j < 4; j++) wmma::fill_fragment(acc[i][j], 0.0f);

    const int sr = tid >> 1;
    const int sh = tid & 1;
    const uint32_t soff = (uint32_t)(sr * (PK * 2) + sh * 16);

    // prefetch chunk 0 into buffer 0
    {
        const size_t asrc = (size_t)(r0 + sr) * EMB + sh * 8;
        const size_t bsrc = (size_t)(e0 + sr) * EMB + sh * 8;
        const uint32_t d = smb + soff;
        cp16(d,          g_aoh + asrc);
        cp16(d + OB_ALO, g_aol + asrc);
        cp16(d + OB_BHI, g_woh + bsrc);
        cp16(d + OB_BLO, g_wol + bsrc);
    }
    CP_COMMIT();

    for (int ic = 0; ic < EMB / 16; ic++) {
        const char* buf = sm + (ic & 1) * OB_SZ;

        CP_WAIT0();
        __syncthreads();

        if (ic + 1 < EMB / 16) {
            const int c1 = (ic + 1) * 16;
            const size_t asrc = (size_t)(r0 + sr) * EMB + c1 + sh * 8;
            const size_t bsrc = (size_t)(e0 + sr) * EMB + c1 + sh * 8;
            const uint32_t d = smb + ((ic + 1) & 1) * OB_SZ + soff;
            cp16(d,          g_aoh + asrc);
            cp16(d + OB_ALO, g_aol + asrc);
            cp16(d + OB_BHI, g_woh + bsrc);
            cp16(d + OB_BLO, g_wol + bsrc);
        }
        CP_COMMIT();

        const __nv_bfloat16* Ahi = (const __nv_bfloat16*)(buf);
        const __nv_bfloat16* Alo = (const __nv_bfloat16*)(buf + OB_ALO);
        const __nv_bfloat16* Bhi = (const __nv_bfloat16*)(buf + OB_BHI);
        const __nv_bfloat16* Blo = (const __nv_bfloat16*)(buf + OB_BLO);

        wmma::fragment<wmma::matrix_a, 16, 16, 16, __nv_bfloat16, wmma::row_major> ah[2], al[2];
#pragma unroll
        for (int i = 0; i < 2; i++) {
            wmma::load_matrix_sync(ah[i], Ahi + (wr * 32 + i * 16) * PK, PK);
            wmma::load_matrix_sync(al[i], Alo + (wr * 32 + i * 16) * PK, PK);
        }
#pragma unroll
        for (int j = 0; j < 4; j++) {
            wmma::fragment<wmma::matrix_b, 16, 16, 16, __nv_bfloat16, wmma::col_major> bh, bl;
            wmma::load_matrix_sync(bh, Bhi + (wc * 64 + j * 16) * PK, PK);
            wmma::load_matrix_sync(bl, Blo + (wc * 64 + j * 16) * PK, PK);
#pragma unroll
            for (int i = 0; i < 2; i++) {
                wmma::mma_sync(acc[i][j], ah[i], bh, acc[i][j]);
                wmma::mma_sync(acc[i][j], ah[i], bl, acc[i][j]);
                wmma::mma_sync(acc[i][j], al[i], bh, acc[i][j]);
            }
        }
    }

    const int r = lane >> 1, cw = lane & 1;
#pragma unroll
    for (int i = 0; i < 2; i++)
#pragma unroll
        for (int j = 0; j < 4; j++) {
            wmma::store_matrix_sync(scr, acc[i][j], PSCR, wmma::mem_row_major);
            __syncwarp();
            const int row = r0 + wr * 32 + i * 16 + r;
            const int col = e0 + wc * 64 + j * 16 + cw * 8;
            const float4 bv0 = *(const float4*)(bo + col);
            const float4 bv1 = *(const float4*)(bo + col + 4);
            const float* s = scr + r * PSCR + cw * 8;
            float4 o0 = make_float4(s[0] + bv0.x, s[1] + bv0.y, s[2] + bv0.z, s[3] + bv0.w);
            float4 o1 = make_float4(s[4] + bv1.x, s[5] + bv1.y, s[6] + bv1.z, s[7] + bv1.w);
            *(float4*)(out + (size_t)row * EMB + col)     = o0;
            *(float4*)(out + (size_t)row * EMB + col + 4) = o1;
            __syncwarp();
        }
}

// ---------------------------------------------------------------------------
extern "C" void kernel_launch(void* const* d_in, const int* in_sizes, int n_in,
                              void* d_out, int out_size)
{
    const float* values  = (const float*)d_in[0];
    const float* queries = (const float*)d_in[1];
    const float* keys    = (const float*)d_in[2];
    const int*   mask    = (const int*)  d_in[3];
    const float* Wv      = (const float*)d_in[4];
    const float* Wk      = (const float*)d_in[5];
    const float* Wq      = (const float*)d_in[6];
    const float* Wo      = (const float*)d_in[7];
    const float* bo      = (const float*)d_in[8];
    float* out = (float*)d_out;

    static bool attr_set = false;
    if (!attr_set) {
        cudaFuncSetAttribute(proj_wmma_kernel,
                             cudaFuncAttributeMaxDynamicSharedMemorySize, PJ_SMEM);
        cudaFuncSetAttribute(attn_mma_kernel,
                             cudaFuncAttributeMaxDynamicSharedMemorySize, ATTN_SMEM);
        cudaFuncSetAttribute(out_wmma_kernel,
                             cudaFuncAttributeMaxDynamicSharedMemorySize, OUT_SMEM);
        attr_set = true;
    }

    mask_pack_kernel<<<(N_B * S_LEN * MWORDS * 32) / 256, 256>>>(mask);
    wo_split_kernel<<<(EMB * EMB) / (256 * 8), 256>>>(Wo);

    dim3 pgrid(S_LEN / 128, N_B * HEADS, 3);
    proj_wmma_kernel<<<pgrid, 256, PJ_SMEM>>>(queries, keys, values, Wq, Wk, Wv);

    dim3 agrid(HEADS, S_LEN / 128, N_B);
    attn_mma_kernel<<<agrid, 256, ATTN_SMEM>>>();

    dim3 ggrid(EMB / 128, (N_B * S_LEN) / 128);
    out_wmma_kernel<<<ggrid, 256, OUT_SMEM>>>(bo, out);
}